// round 5
// baseline (speedup 1.0000x reference)
#include <cuda_runtime.h>
#include <math.h>

#define Bv 4
#define Cv 32
#define Sv 64
#define Hv 256
#define ROWS (Cv * Sv)          // 2048 rows per batch
#define NEG_BIG (-1e10f)

#define KT 32                   // K-chunk
#define PW 132                  // padded smem row stride (floats)

// Scratch (static device arrays; no runtime allocation allowed)
__device__ float g_proj[Bv * ROWS * Hv];       // 8 MB
__device__ float g_w[Bv * Cv * Cv * Sv];       // 2 MB

typedef unsigned long long u64;

// ---------------- packed f32x2 helpers (sm_103a dual-lane fp32) -------------
__device__ __forceinline__ u64 splat2(float v) {
    u64 r; asm("mov.b64 %0, {%1, %1};" : "=l"(r) : "f"(v)); return r;
}
__device__ __forceinline__ u64 pack2(float x, float y) {
    u64 r; asm("mov.b64 %0, {%1, %2};" : "=l"(r) : "f"(x), "f"(y)); return r;
}
__device__ __forceinline__ void ffma2(u64& d, u64 a, u64 b) {
    asm("fma.rn.f32x2 %0, %1, %2, %0;" : "+l"(d) : "l"(a), "l"(b));
}
__device__ __forceinline__ float lo32(u64 v) { return __uint_as_float((unsigned)v); }
__device__ __forceinline__ float hi32(u64 v) { return __uint_as_float((unsigned)(v >> 32)); }

// ---------------- MUFU-free sigmoid (all fma/alu pipe) ----------------------
// exp(x) via 2^t with magic-number rounding + deg-5 Taylor on [-0.5,0.5],
// reciprocal via bit-trick seed + 3 Newton iterations. abs err < ~1e-6.
__device__ __forceinline__ float fast_sigmoid(float x) {
    x = fminf(30.0f, fmaxf(-30.0f, x));
    float t  = x * 1.4426950408889634f;       // x * log2(e), |t| <= 43.3
    float r  = t + 12582912.0f;               // round-to-nearest-int (2^23*1.5)
    float fi = r - 12582912.0f;
    float f  = t - fi;                        // f in [-0.5, 0.5]
    float p  = 1.3333558146428443e-3f;        // ln2^5/120
    p = fmaf(p, f, 9.6181291076284772e-3f);   // ln2^4/24
    p = fmaf(p, f, 5.5504108664821580e-2f);   // ln2^3/6
    p = fmaf(p, f, 2.4022650695910072e-1f);   // ln2^2/2
    p = fmaf(p, f, 6.9314718055994531e-1f);   // ln2
    p = fmaf(p, f, 1.0f);                     // p = 2^f in [0.707, 1.415]
    int ei = __float_as_int(r) - 0x4B400000;  // integer part of t
    float e = __int_as_float(__float_as_int(p) + (ei << 23));  // e = exp(x)
    float d = 1.0f + e;
    float y = __int_as_float(0x7EF311C3 - __float_as_int(d));  // ~rcp seed
    y = y * fmaf(-d, y, 2.0f);
    y = y * fmaf(-d, y, 2.0f);
    y = y * fmaf(-d, y, 2.0f);
    return e * y;                             // e / (1 + e) = sigmoid(x)
}

// ---------------------------------------------------------------------------
// Packed NT-GEMM mainloop: C[r,c] = sum_k A[r,k]*B[c,k]
// MT x 128 tile (MT in {64,128}), K=256. Tiles stored transposed in smem
// (sA[k][r]). Per-thread fragment: RI x 8, accumulated as RI x 4 f32x2 pairs.
// Column pairing: accP[i][q] = cols {2q, 2q+1}  (low lane = even col).
// ---------------------------------------------------------------------------
template<int MT>
__device__ __forceinline__ void gemm_mainloop_x2(
    const float* __restrict__ Ab,   // A + rowBase*256
    const float* __restrict__ Bb,   // B + colBase*256
    float* sA, float* sB, u64 accP[MT / 16][4], int tid)
{
    const int tx = tid & 15;
    const int ty = tid >> 4;
    constexpr int RI = MT / 16;

    for (int k0 = 0; k0 < Hv; k0 += KT) {
        #pragma unroll
        for (int p = 0; p < MT / 32; p++) {
            int idx = tid + p * 256;
            int r   = idx >> 3;
            int c4  = (idx & 7) << 2;
            float4 va = *(const float4*)(Ab + r * Hv + k0 + c4);
            sA[(c4 + 0) * PW + r] = va.x;
            sA[(c4 + 1) * PW + r] = va.y;
            sA[(c4 + 2) * PW + r] = va.z;
            sA[(c4 + 3) * PW + r] = va.w;
        }
        #pragma unroll
        for (int p = 0; p < 4; p++) {
            int idx = tid + p * 256;
            int r   = idx >> 3;
            int c4  = (idx & 7) << 2;
            float4 vb = *(const float4*)(Bb + r * Hv + k0 + c4);
            sB[(c4 + 0) * PW + r] = vb.x;
            sB[(c4 + 1) * PW + r] = vb.y;
            sB[(c4 + 2) * PW + r] = vb.z;
            sB[(c4 + 3) * PW + r] = vb.w;
        }
        __syncthreads();

        #pragma unroll 4
        for (int k = 0; k < KT; k++) {
            float4 b0 = *(const float4*)(sB + k * PW + tx * 8);
            float4 b1 = *(const float4*)(sB + k * PW + tx * 8 + 4);
            u64 bP[4];
            bP[0] = pack2(b0.x, b0.y);
            bP[1] = pack2(b0.z, b0.w);
            bP[2] = pack2(b1.x, b1.y);
            bP[3] = pack2(b1.z, b1.w);

            float av[RI];
            {
                float4 a0 = *(const float4*)(sA + k * PW + ty * RI);
                av[0] = a0.x; av[1] = a0.y; av[2] = a0.z; av[3] = a0.w;
                if (RI == 8) {
                    float4 a1 = *(const float4*)(sA + k * PW + ty * RI + 4);
                    av[4] = a1.x; av[5] = a1.y; av[6] = a1.z; av[7] = a1.w;
                }
            }
            #pragma unroll
            for (int i = 0; i < RI; i++) {
                u64 aS = splat2(av[i]);
                #pragma unroll
                for (int q = 0; q < 4; q++) ffma2(accP[i][q], aS, bP[q]);
            }
        }
        __syncthreads();
    }
}

// ---------------------------------------------------------------------------
// Kernel 1: proj[m,g] = sum_h inputs[m,h] * W[g,h]   (M=8192, N=256, K=256)
// 64x128 tiles -> 256 CTAs (full wave+), packed fp32.
// ---------------------------------------------------------------------------
__global__ __launch_bounds__(256, 2)
void proj_kernel(const float* __restrict__ inp, const float* __restrict__ W)
{
    __shared__ float sA[KT * PW];
    __shared__ float sB[KT * PW];

    const int tid = threadIdx.x;
    const int rowBase = blockIdx.y * 64;
    const int colBase = blockIdx.x * 128;

    u64 accP[4][4];
    #pragma unroll
    for (int i = 0; i < 4; i++)
        #pragma unroll
        for (int q = 0; q < 4; q++) accP[i][q] = 0ull;

    gemm_mainloop_x2<64>(inp + (size_t)rowBase * Hv, W + (size_t)colBase * Hv,
                         sA, sB, accP, tid);

    const int tx = tid & 15;
    const int ty = tid >> 4;
    #pragma unroll
    for (int i = 0; i < 4; i++) {
        float4 v0 = make_float4(lo32(accP[i][0]), hi32(accP[i][0]),
                                lo32(accP[i][1]), hi32(accP[i][1]));
        float4 v1 = make_float4(lo32(accP[i][2]), hi32(accP[i][2]),
                                lo32(accP[i][3]), hi32(accP[i][3]));
        float* dst = g_proj + (size_t)(rowBase + ty * 4 + i) * Hv + colBase + tx * 8;
        *(float4*)dst = v0;
        *(float4*)(dst + 4) = v1;
    }
}

// ---------------------------------------------------------------------------
// Kernel 2: per-batch scores GEMM (2048x2048x256), sigmoid epilogue writing
// att[B,C,C,S,S], fused reduction w[b,i,j,t] = sum_s aself[b,i,s]*att[...s,t].
// ---------------------------------------------------------------------------
__global__ __launch_bounds__(256, 2)
void att_kernel(const float* __restrict__ inp, const float* __restrict__ mask,
                const float* __restrict__ aself, float* __restrict__ att_out)
{
    __shared__ float sA[KT * PW];
    __shared__ float sB[KT * PW];
    __shared__ float s_wp[16 * 128];
    __shared__ float s_as[128];

    const int tid = threadIdx.x;
    const int b = blockIdx.z;
    const int rowBase = blockIdx.y * 128;
    const int colBase = blockIdx.x * 128;

    if (tid < 128) s_as[tid] = aself[b * ROWS + rowBase + tid];
    // visibility guaranteed by first __syncthreads inside mainloop

    u64 accP[8][4];
    #pragma unroll
    for (int i = 0; i < 8; i++)
        #pragma unroll
        for (int q = 0; q < 4; q++) accP[i][q] = 0ull;

    const float* Ab = g_proj + (size_t)(b * ROWS + rowBase) * Hv;
    const float* Bb = inp    + (size_t)(b * ROWS + colBase) * Hv;
    gemm_mainloop_x2<128>(Ab, Bb, sA, sB, accP, tid);

    const int tx = tid & 15;
    const int ty = tid >> 4;

    float mcol[8], wpart[8];
    #pragma unroll
    for (int j = 0; j < 8; j++) {
        mcol[j] = (1.0f - mask[b * ROWS + colBase + tx * 8 + j]) * NEG_BIG;
        wpart[j] = 0.f;
    }

    const int i_idx = blockIdx.y * 2 + (ty >> 3);
    const int j_idx = blockIdx.x * 2 + (tx >> 3);
    const int s0 = (ty * 8) & 63;
    const int t0 = (tx * 8) & 63;
    float* attB = att_out + (((size_t)((b * Cv + i_idx) * Cv + j_idx)) << 12) + t0;

    #pragma unroll
    for (int i = 0; i < 8; i++) {
        float asv = s_as[ty * 8 + i];
        float rowv[8];
        #pragma unroll
        for (int q = 0; q < 4; q++) {
            rowv[2 * q + 0] = lo32(accP[i][q]);
            rowv[2 * q + 1] = hi32(accP[i][q]);
        }
        #pragma unroll
        for (int j = 0; j < 8; j++) {
            float a = fast_sigmoid(rowv[j] + mcol[j]);
            rowv[j] = a;
            wpart[j] += a * asv;
        }
        float4 v0 = make_float4(rowv[0], rowv[1], rowv[2], rowv[3]);
        float4 v1 = make_float4(rowv[4], rowv[5], rowv[6], rowv[7]);
        float* dst = attB + (size_t)(s0 + i) * 64;
        *(float4*)dst = v0;
        *(float4*)(dst + 4) = v1;
    }

    // deterministic per-column reduction of wpart across the 16 thread-rows
    #pragma unroll
    for (int j = 0; j < 8; j++) s_wp[ty * 128 + tx * 8 + j] = wpart[j];
    __syncthreads();

    {
        int rh = tid >> 7;        // which i-half of the tile
        int lc = tid & 127;       // local column 0..127
        float s = 0.f;
        #pragma unroll
        for (int yy = 0; yy < 8; yy++) s += s_wp[(rh * 8 + yy) * 128 + lc];
        int ii = blockIdx.y * 2 + rh;
        int jj = blockIdx.x * 2 + (lc >> 6);
        int tt = lc & 63;
        g_w[((b * Cv + ii) * Cv + jj) * Sv + tt] = s;
    }
}

// ---------------------------------------------------------------------------
// Kernel 3: fused[b,i,j,h] = sum_t w[b,i,j,t] * inputs[b,j,t,h]
// ---------------------------------------------------------------------------
__global__ __launch_bounds__(256)
void fused_kernel(const float* __restrict__ inp, float* __restrict__ fused)
{
    const int j = blockIdx.x;
    const int b = blockIdx.y;
    const int h = threadIdx.x;

    const float* X = inp + (size_t)((b * Cv + j) * Sv) * Hv;
    float xc[64];
    #pragma unroll
    for (int t = 0; t < 64; t++) xc[t] = X[(size_t)t * Hv + h];

    __shared__ float sw[64];
    for (int i = 0; i < Cv; i++) {
        if (h < 64) sw[h] = g_w[((b * Cv + i) * Cv + j) * Sv + h];
        __syncthreads();
        float acc = 0.f;
        #pragma unroll
        for (int t = 0; t < 64; t++) acc = fmaf(sw[t], xc[t], acc);
        fused[(size_t)((b * Cv + i) * Cv + j) * Hv + h] = acc;
        __syncthreads();
    }
}

// ---------------------------------------------------------------------------
extern "C" void kernel_launch(void* const* d_in, const int* in_sizes, int n_in,
                              void* d_out, int out_size)
{
    const float* inputs = (const float*)d_in[0];   // [B,C,S,H]
    const float* mask   = (const float*)d_in[1];   // [B,C,S]
    const float* aself  = (const float*)d_in[2];   // [B,C,S]
    const float* W      = (const float*)d_in[3];   // [H,H]

    // Output tuple flattened in order: fused [B,C,C,H] then att [B,C,C,S,S]
    float* fused = (float*)d_out;
    float* att   = (float*)d_out + (size_t)Bv * Cv * Cv * Hv;

    proj_kernel <<<dim3(2, 128, 1), 256>>>(inputs, W);
    att_kernel  <<<dim3(16, 16, Bv), 256>>>(inputs, mask, aself, att);
    fused_kernel<<<dim3(Cv, Bv, 1), 256>>>(inputs, fused);
}

// round 7
// speedup vs baseline: 1.4632x; 1.4632x over previous
#include <cuda_runtime.h>
#include <cuda_bf16.h>
#include <math.h>
#include <stdint.h>

#define Bv 4
#define Cv 32
#define Sv 64
#define Hv 256
#define ROWS 2048
#define NEG_BIG (-1e10f)

#define KT 32
#define PW 132

#define KP 768            // packed K' = 3 * 256 bf16
#define KC 32             // bf16 per pipeline chunk
#define NCH 24            // KP / KC
#define SROW 80           // smem row stride in bytes (64B data + 16B pad)
#define TILEB (128 * SROW)        // 10240 B per operand tile
#define STAGEB (2 * TILEB)        // A + B per stage

// ---- scratch (static device arrays) ----------------------------------------
__device__ __nv_bfloat16 g_Apack[(size_t)Bv * ROWS * KP];   // [hi | lo | hi] of proj
__device__ __nv_bfloat16 g_Bpack[(size_t)Bv * ROWS * KP];   // [hi | hi | lo] of inputs
__device__ float g_w[Bv * Cv * Cv * Sv];

// ---- helpers ---------------------------------------------------------------
__device__ __forceinline__ uint32_t s2u(const void* p) {
    uint32_t a;
    asm("{ .reg .u64 t; cvta.to.shared.u64 t, %1; cvt.u32.u64 %0, t; }"
        : "=r"(a) : "l"(p));
    return a;
}
__device__ __forceinline__ void cpasync16(uint32_t s, const void* g) {
    asm volatile("cp.async.cg.shared.global [%0], [%1], 16;" :: "r"(s), "l"(g));
}
__device__ __forceinline__ void ldsm4(uint32_t r[4], uint32_t addr) {
    asm volatile("ldmatrix.sync.aligned.m8n8.x4.shared.b16 {%0,%1,%2,%3}, [%4];"
        : "=r"(r[0]), "=r"(r[1]), "=r"(r[2]), "=r"(r[3]) : "r"(addr));
}
__device__ __forceinline__ void mma16816(float c[4], const uint32_t a[4],
                                         const uint32_t b[2]) {
    asm volatile(
        "mma.sync.aligned.m16n8k16.row.col.f32.bf16.bf16.f32 "
        "{%0,%1,%2,%3}, {%4,%5,%6,%7}, {%8,%9}, {%0,%1,%2,%3};"
        : "+f"(c[0]), "+f"(c[1]), "+f"(c[2]), "+f"(c[3])
        : "r"(a[0]), "r"(a[1]), "r"(a[2]), "r"(a[3]), "r"(b[0]), "r"(b[1]));
}

// ---- MUFU-free sigmoid (validated R4/R5) -----------------------------------
__device__ __forceinline__ float fast_sigmoid(float x) {
    x = fminf(30.0f, fmaxf(-30.0f, x));
    float t  = x * 1.4426950408889634f;
    float r  = t + 12582912.0f;
    float fi = r - 12582912.0f;
    float f  = t - fi;
    float p  = 1.3333558146428443e-3f;
    p = fmaf(p, f, 9.6181291076284772e-3f);
    p = fmaf(p, f, 5.5504108664821580e-2f);
    p = fmaf(p, f, 2.4022650695910072e-1f);
    p = fmaf(p, f, 6.9314718055994531e-1f);
    p = fmaf(p, f, 1.0f);
    int ei = __float_as_int(r) - 0x4B400000;
    float e = __int_as_float(__float_as_int(p) + (ei << 23));
    float d = 1.0f + e;
    float y = __int_as_float(0x7EF311C3 - __float_as_int(d));
    y = y * fmaf(-d, y, 2.0f);
    y = y * fmaf(-d, y, 2.0f);
    y = y * fmaf(-d, y, 2.0f);
    return e * y;
}

// ---------------------------------------------------------------------------
// Kernel 0: pack inputs -> Bpack = [hi | hi | lo]
// ---------------------------------------------------------------------------
__global__ __launch_bounds__(256)
void pack_inputs(const float* __restrict__ inp)
{
    int idx = blockIdx.x * 256 + threadIdx.x;    // < Bv*ROWS*Hv = 2097152
    float x = inp[idx];
    __nv_bfloat16 hi = __float2bfloat16(x);
    __nv_bfloat16 lo = __float2bfloat16(x - __bfloat162float(hi));
    int row = idx >> 8, k = idx & 255;
    size_t base = (size_t)row * KP;
    g_Bpack[base + k]       = hi;
    g_Bpack[base + 256 + k] = hi;
    g_Bpack[base + 512 + k] = lo;
}

// ---------------------------------------------------------------------------
// Kernel 1: proj = inputs @ W^T  (scalar fp32, R3 mainloop); epilogue writes
//           Apack = [hi | lo | hi] of proj.
// ---------------------------------------------------------------------------
__global__ __launch_bounds__(256, 2)
void proj_kernel(const float* __restrict__ inp, const float* __restrict__ W)
{
    __shared__ float sA[KT * PW];
    __shared__ float sB[KT * PW];

    const int tid = threadIdx.x;
    const int tx = tid & 15;
    const int ty = tid >> 4;
    const int rowBase = blockIdx.y * 128;
    const int colBase = blockIdx.x * 128;

    const float* Ab = inp + (size_t)rowBase * Hv;
    const float* Bb = W   + (size_t)colBase * Hv;

    float acc[8][8];
    #pragma unroll
    for (int i = 0; i < 8; i++)
        #pragma unroll
        for (int j = 0; j < 8; j++) acc[i][j] = 0.f;

    for (int k0 = 0; k0 < Hv; k0 += KT) {
        #pragma unroll
        for (int p = 0; p < 4; p++) {
            int idx = tid + p * 256;
            int r   = idx >> 3;
            int c4  = (idx & 7) << 2;
            float4 va = *(const float4*)(Ab + r * Hv + k0 + c4);
            float4 vb = *(const float4*)(Bb + r * Hv + k0 + c4);
            sA[(c4 + 0) * PW + r] = va.x;
            sA[(c4 + 1) * PW + r] = va.y;
            sA[(c4 + 2) * PW + r] = va.z;
            sA[(c4 + 3) * PW + r] = va.w;
            sB[(c4 + 0) * PW + r] = vb.x;
            sB[(c4 + 1) * PW + r] = vb.y;
            sB[(c4 + 2) * PW + r] = vb.z;
            sB[(c4 + 3) * PW + r] = vb.w;
        }
        __syncthreads();

        #pragma unroll 1
        for (int kk = 0; kk < KT; kk += 8) {
            #pragma unroll
            for (int u = 0; u < 8; u++) {
                int k = kk + u;
                const float4 a0 = *(const float4*)(sA + k * PW + ty * 8);
                const float4 a1 = *(const float4*)(sA + k * PW + ty * 8 + 4);
                const float4 b0 = *(const float4*)(sB + k * PW + tx * 8);
                const float4 b1 = *(const float4*)(sB + k * PW + tx * 8 + 4);
                float av[8] = {a0.x, a0.y, a0.z, a0.w, a1.x, a1.y, a1.z, a1.w};
                float bv[8] = {b0.x, b0.y, b0.z, b0.w, b1.x, b1.y, b1.z, b1.w};
                #pragma unroll
                for (int i = 0; i < 8; i++)
                    #pragma unroll
                    for (int j = 0; j < 8; j++)
                        acc[i][j] = fmaf(av[i], bv[j], acc[i][j]);
            }
        }
        __syncthreads();
    }

    #pragma unroll
    for (int i = 0; i < 8; i++) {
        int row = rowBase + ty * 8 + i;
        size_t base = (size_t)row * KP + colBase + tx * 8;
        #pragma unroll
        for (int j = 0; j < 8; j++) {
            float x = acc[i][j];
            __nv_bfloat16 hi = __float2bfloat16(x);
            __nv_bfloat16 lo = __float2bfloat16(x - __bfloat162float(hi));
            g_Apack[base + j]       = hi;
            g_Apack[base + 256 + j] = lo;
            g_Apack[base + 512 + j] = hi;
        }
    }
}

// ---------------------------------------------------------------------------
// Kernel 2: att GEMM via mma.sync (HMMA bf16, fp32 accum), 128x128 tile,
// K'=768, cp.async 2-stage pipeline. Epilogue: sigmoid + att store + per-warp
// w reduction (each warp's 64 rows = one full sentence i-block).
// ---------------------------------------------------------------------------
__global__ __launch_bounds__(256)
void att_kernel(const float* __restrict__ mask, const float* __restrict__ aself,
                float* __restrict__ att_out)
{
    __shared__ __align__(128) char smem[2 * STAGEB];   // 40 KB

    const int tid = threadIdx.x;
    const int w = tid >> 5, l = tid & 31;
    const int mw = w >> 2, nw = w & 3;       // warp grid 2 (M) x 4 (N)
    const int b = blockIdx.z;
    const int rowBase = blockIdx.y * 128;
    const int colBase = blockIdx.x * 128;

    const char* Ag = (const char*)(g_Apack + (size_t)(b * ROWS + rowBase) * KP);
    const char* Bg = (const char*)(g_Bpack + (size_t)(b * ROWS + colBase) * KP);
    const uint32_t sb = s2u(smem);

    // cp.async per-thread mapping: 128 rows x 4 x16B per tile; 2 rows/thread
    const int r0 = tid >> 2;
    const int c0 = (tid & 3) * 16;

    // ldmatrix per-lane base offsets
    const int q = l >> 3, lr = l & 7;
    const uint32_t aoff = (uint32_t)((mw * 64 + (q & 1) * 8 + lr) * SROW + (q >> 1) * 16);
    const uint32_t boff = (uint32_t)(TILEB + (nw * 32 + (q >> 1) * 8 + lr) * SROW + (q & 1) * 16);

    float acc[4][4][4];
    #pragma unroll
    for (int i = 0; i < 4; i++)
        #pragma unroll
        for (int j = 0; j < 4; j++)
            #pragma unroll
            for (int v = 0; v < 4; v++) acc[i][j][v] = 0.f;

    auto issue = [&](int c, int stage) {
        uint32_t st = sb + stage * STAGEB;
        size_t gk = (size_t)c * (KC * 2);
        #pragma unroll
        for (int p = 0; p < 2; p++) {
            int rr = r0 + p * 64;
            cpasync16(st + rr * SROW + c0,         Ag + (size_t)rr * (KP * 2) + gk + c0);
            cpasync16(st + TILEB + rr * SROW + c0, Bg + (size_t)rr * (KP * 2) + gk + c0);
        }
        asm volatile("cp.async.commit_group;" ::: "memory");
    };

    issue(0, 0);
    issue(1, 1);

    for (int c = 0; c < NCH; c++) {
        if (c >= NCH - 2) asm volatile("cp.async.wait_group 0;" ::: "memory");
        else              asm volatile("cp.async.wait_group 1;" ::: "memory");
        __syncthreads();

        uint32_t st = sb + (c & 1) * STAGEB;
        #pragma unroll
        for (int ks = 0; ks < 2; ks++) {
            uint32_t a_[4][4];
            uint32_t b_[4][2];
            #pragma unroll
            for (int i = 0; i < 4; i++)
                ldsm4(a_[i], st + aoff + i * 16 * SROW + ks * 32);
            #pragma unroll
            for (int jj = 0; jj < 2; jj++) {
                uint32_t t4[4];
                ldsm4(t4, st + boff + jj * 16 * SROW + ks * 32);
                b_[jj * 2][0]     = t4[0]; b_[jj * 2][1]     = t4[1];
                b_[jj * 2 + 1][0] = t4[2]; b_[jj * 2 + 1][1] = t4[3];
            }
            #pragma unroll
            for (int i = 0; i < 4; i++)
                #pragma unroll
                for (int j = 0; j < 4; j++)
                    mma16816(acc[i][j], a_[i], b_[j]);
        }
        __syncthreads();
        if (c + 2 < NCH) issue(c + 2, c & 1);
    }

    // ---- epilogue ----
    const int lq = l >> 2, lrm = l & 3;
    const int ii  = blockIdx.y * 2 + mw;
    const int jjg = blockIdx.x * 2 + (nw >> 1);

    float asv[4][2];
    #pragma unroll
    for (int i = 0; i < 4; i++)
        #pragma unroll
        for (int h = 0; h < 2; h++)
            asv[i][h] = aself[b * ROWS + rowBase + mw * 64 + i * 16 + lq + 8 * h];

    float mc[4][2];
    #pragma unroll
    for (int j = 0; j < 4; j++) {
        int tc = nw * 32 + j * 8 + lrm * 2;
        mc[j][0] = (1.0f - mask[b * ROWS + colBase + tc])     * NEG_BIG;
        mc[j][1] = (1.0f - mask[b * ROWS + colBase + tc + 1]) * NEG_BIG;
    }

    float wpart[4][2];
    #pragma unroll
    for (int j = 0; j < 4; j++) { wpart[j][0] = 0.f; wpart[j][1] = 0.f; }

    float* attB = att_out + (((size_t)((b * Cv + ii) * Cv + jjg)) << 12);

    #pragma unroll
    for (int i = 0; i < 4; i++) {
        int s_lo = i * 16 + lq;
        #pragma unroll
        for (int j = 0; j < 4; j++) {
            int tcol = (nw & 1) * 32 + j * 8 + lrm * 2;
            float a0 = fast_sigmoid(acc[i][j][0] + mc[j][0]);
            float a1 = fast_sigmoid(acc[i][j][1] + mc[j][1]);
            float a2 = fast_sigmoid(acc[i][j][2] + mc[j][0]);
            float a3 = fast_sigmoid(acc[i][j][3] + mc[j][1]);
            *(float2*)(attB + (size_t)s_lo * 64 + tcol)       = make_float2(a0, a1);
            *(float2*)(attB + (size_t)(s_lo + 8) * 64 + tcol) = make_float2(a2, a3);
            wpart[j][0] += a0 * asv[i][0] + a2 * asv[i][1];
            wpart[j][1] += a1 * asv[i][0] + a3 * asv[i][1];
        }
    }

    // reduce across the 8 row-groups (lq) within the warp
    #pragma unroll
    for (int d = 4; d <= 16; d <<= 1)
        #pragma unroll
        for (int j = 0; j < 4; j++) {
            wpart[j][0] += __shfl_xor_sync(0xffffffffu, wpart[j][0], d);
            wpart[j][1] += __shfl_xor_sync(0xffffffffu, wpart[j][1], d);
        }
    if (lq == 0) {
        #pragma unroll
        for (int j = 0; j < 4; j++) {
            int tcol = (nw & 1) * 32 + j * 8 + lrm * 2;
            *(float2*)(g_w + ((size_t)((b * Cv + ii) * Cv + jjg)) * 64 + tcol)
                = make_float2(wpart[j][0], wpart[j][1]);
        }
    }
}

// ---------------------------------------------------------------------------
// Kernel 3: fused[b,i,j,h] = sum_t w[b,i,j,t] * inputs[b,j,t,h]
// ---------------------------------------------------------------------------
__global__ __launch_bounds__(256)
void fused_kernel(const float* __restrict__ inp, float* __restrict__ fused)
{
    const int j = blockIdx.x;
    const int b = blockIdx.y;
    const int h = threadIdx.x;

    const float* X = inp + (size_t)((b * Cv + j) * Sv) * Hv;
    float xc[64];
    #pragma unroll
    for (int t = 0; t < 64; t++) xc[t] = X[(size_t)t * Hv + h];

    __shared__ float sw[64];
    for (int i = 0; i < Cv; i++) {
        if (h < 64) sw[h] = g_w[((b * Cv + i) * Cv + j) * Sv + h];
        __syncthreads();
        float acc = 0.f;
        #pragma unroll
        for (int t = 0; t < 64; t++) acc = fmaf(sw[t], xc[t], acc);
        fused[(size_t)((b * Cv + i) * Cv + j) * Hv + h] = acc;
        __syncthreads();
    }
}

// ---------------------------------------------------------------------------
extern "C" void kernel_launch(void* const* d_in, const int* in_sizes, int n_in,
                              void* d_out, int out_size)
{
    const float* inputs = (const float*)d_in[0];   // [B,C,S,H]
    const float* mask   = (const float*)d_in[1];   // [B,C,S]
    const float* aself  = (const float*)d_in[2];   // [B,C,S]
    const float* W      = (const float*)d_in[3];   // [H,H]

    float* fused = (float*)d_out;                                  // [B,C,C,H]
    float* att   = (float*)d_out + (size_t)Bv * Cv * Cv * Hv;      // [B,C,C,S,S]

    pack_inputs<<<8192, 256>>>(inputs);
    proj_kernel<<<dim3(2, 64, 1), 256>>>(inputs, W);
    att_kernel<<<dim3(16, 16, Bv), 256>>>(mask, aself, att);
    fused_kernel<<<dim3(Cv, Bv, 1), 256>>>(inputs, fused);
}

// round 8
// speedup vs baseline: 1.8835x; 1.2872x over previous
#include <cuda_runtime.h>
#include <cuda_bf16.h>
#include <math.h>
#include <stdint.h>

#define Bv 4
#define Cv 32
#define Sv 64
#define Hv 256
#define ROWS 2048
#define NEG_BIG (-1e10f)

#define KP 768            // packed K' = 3 * 256 bf16
#define KC 32             // bf16 per pipeline chunk
#define NCH 24            // KP / KC
#define SROW 80           // smem row stride in bytes (64B data + 16B pad)
#define TILEB (128 * SROW)        // 10240 B per operand tile
#define STAGEB (2 * TILEB)        // A + B per stage

// ---- scratch (static device arrays) ----------------------------------------
__device__ __nv_bfloat16 g_Apack[(size_t)Bv * ROWS * KP];   // [hi | lo | hi] of proj
__device__ __nv_bfloat16 g_Bpack[(size_t)Bv * ROWS * KP];   // [hi | hi | lo] of inputs
__device__ __nv_bfloat16 g_Wpack[(size_t)Hv * KP];          // [hi | lo | hi] of W
__device__ float g_w[Bv * Cv * Cv * Sv];

// ---- helpers ---------------------------------------------------------------
__device__ __forceinline__ uint32_t s2u(const void* p) {
    uint32_t a;
    asm("{ .reg .u64 t; cvta.to.shared.u64 t, %1; cvt.u32.u64 %0, t; }"
        : "=r"(a) : "l"(p));
    return a;
}
__device__ __forceinline__ void cpasync16(uint32_t s, const void* g) {
    asm volatile("cp.async.cg.shared.global [%0], [%1], 16;" :: "r"(s), "l"(g));
}
__device__ __forceinline__ void ldsm4(uint32_t r[4], uint32_t addr) {
    asm volatile("ldmatrix.sync.aligned.m8n8.x4.shared.b16 {%0,%1,%2,%3}, [%4];"
        : "=r"(r[0]), "=r"(r[1]), "=r"(r[2]), "=r"(r[3]) : "r"(addr));
}
__device__ __forceinline__ void mma16816(float c[4], const uint32_t a[4],
                                         const uint32_t b[2]) {
    asm volatile(
        "mma.sync.aligned.m16n8k16.row.col.f32.bf16.bf16.f32 "
        "{%0,%1,%2,%3}, {%4,%5,%6,%7}, {%8,%9}, {%0,%1,%2,%3};"
        : "+f"(c[0]), "+f"(c[1]), "+f"(c[2]), "+f"(c[3])
        : "r"(a[0]), "r"(a[1]), "r"(a[2]), "r"(a[3]), "r"(b[0]), "r"(b[1]));
}

// ---- MUFU-free sigmoid (validated R4-R7) -----------------------------------
__device__ __forceinline__ float fast_sigmoid(float x) {
    x = fminf(30.0f, fmaxf(-30.0f, x));
    float t  = x * 1.4426950408889634f;
    float r  = t + 12582912.0f;
    float fi = r - 12582912.0f;
    float f  = t - fi;
    float p  = 1.3333558146428443e-3f;
    p = fmaf(p, f, 9.6181291076284772e-3f);
    p = fmaf(p, f, 5.5504108664821580e-2f);
    p = fmaf(p, f, 2.4022650695910072e-1f);
    p = fmaf(p, f, 6.9314718055994531e-1f);
    p = fmaf(p, f, 1.0f);
    int ei = __float_as_int(r) - 0x4B400000;
    float e = __int_as_float(__float_as_int(p) + (ei << 23));
    float d = 1.0f + e;
    float y = __int_as_float(0x7EF311C3 - __float_as_int(d));
    y = y * fmaf(-d, y, 2.0f);
    y = y * fmaf(-d, y, 2.0f);
    y = y * fmaf(-d, y, 2.0f);
    return e * y;
}

// ---------------------------------------------------------------------------
// Kernel 0a: pack inputs -> Bpack = [hi | hi | lo]
// ---------------------------------------------------------------------------
__global__ __launch_bounds__(256)
void pack_inputs(const float* __restrict__ inp)
{
    int idx = blockIdx.x * 256 + threadIdx.x;    // < Bv*ROWS*Hv = 2097152
    float x = inp[idx];
    __nv_bfloat16 hi = __float2bfloat16(x);
    __nv_bfloat16 lo = __float2bfloat16(x - __bfloat162float(hi));
    int row = idx >> 8, k = idx & 255;
    size_t base = (size_t)row * KP;
    g_Bpack[base + k]       = hi;
    g_Bpack[base + 256 + k] = hi;
    g_Bpack[base + 512 + k] = lo;
}

// ---------------------------------------------------------------------------
// Kernel 0b: pack W -> Wpack = [hi | lo | hi]
// (pairs with inputs-pack [hi|hi|lo]: products hi*hi + hi*lo + lo*hi)
// ---------------------------------------------------------------------------
__global__ __launch_bounds__(256)
void pack_W(const float* __restrict__ W)
{
    int idx = blockIdx.x * 256 + threadIdx.x;    // < 65536
    float x = W[idx];
    __nv_bfloat16 hi = __float2bfloat16(x);
    __nv_bfloat16 lo = __float2bfloat16(x - __bfloat162float(hi));
    int row = idx >> 8, k = idx & 255;
    size_t base = (size_t)row * KP;
    g_Wpack[base + k]       = hi;
    g_Wpack[base + 256 + k] = lo;
    g_Wpack[base + 512 + k] = hi;
}

// ---------------------------------------------------------------------------
// Shared HMMA mainloop (128x128 tile, K'=768, cp.async 2-stage).
// Accumulates into acc[4][4][4]; warp grid 2(M) x 4(N).
// ---------------------------------------------------------------------------
__device__ __forceinline__ void hmma_mainloop(
    const char* __restrict__ Ag, const char* __restrict__ Bg,
    char* smem, float acc[4][4][4], int tid)
{
    const int w = tid >> 5, l = tid & 31;
    const int mw = w >> 2, nw = w & 3;
    const uint32_t sb = s2u(smem);

    const int r0 = tid >> 2;
    const int c0 = (tid & 3) * 16;

    const int q = l >> 3, lr = l & 7;
    const uint32_t aoff = (uint32_t)((mw * 64 + (q & 1) * 8 + lr) * SROW + (q >> 1) * 16);
    const uint32_t boff = (uint32_t)(TILEB + (nw * 32 + (q >> 1) * 8 + lr) * SROW + (q & 1) * 16);

    auto issue = [&](int c, int stage) {
        uint32_t st = sb + stage * STAGEB;
        size_t gk = (size_t)c * (KC * 2);
        #pragma unroll
        for (int p = 0; p < 2; p++) {
            int rr = r0 + p * 64;
            cpasync16(st + rr * SROW + c0,         Ag + (size_t)rr * (KP * 2) + gk + c0);
            cpasync16(st + TILEB + rr * SROW + c0, Bg + (size_t)rr * (KP * 2) + gk + c0);
        }
        asm volatile("cp.async.commit_group;" ::: "memory");
    };

    issue(0, 0);
    issue(1, 1);

    for (int c = 0; c < NCH; c++) {
        if (c >= NCH - 2) asm volatile("cp.async.wait_group 0;" ::: "memory");
        else              asm volatile("cp.async.wait_group 1;" ::: "memory");
        __syncthreads();

        uint32_t st = sb + (c & 1) * STAGEB;
        #pragma unroll
        for (int ks = 0; ks < 2; ks++) {
            uint32_t a_[4][4];
            uint32_t b_[4][2];
            #pragma unroll
            for (int i = 0; i < 4; i++)
                ldsm4(a_[i], st + aoff + i * 16 * SROW + ks * 32);
            #pragma unroll
            for (int jj = 0; jj < 2; jj++) {
                uint32_t t4[4];
                ldsm4(t4, st + boff + jj * 16 * SROW + ks * 32);
                b_[jj * 2][0]     = t4[0]; b_[jj * 2][1]     = t4[1];
                b_[jj * 2 + 1][0] = t4[2]; b_[jj * 2 + 1][1] = t4[3];
            }
            #pragma unroll
            for (int i = 0; i < 4; i++)
                #pragma unroll
                for (int j = 0; j < 4; j++)
                    mma16816(acc[i][j], a_[i], b_[j]);
        }
        __syncthreads();
        if (c + 2 < NCH) issue(c + 2, c & 1);
    }
}

// ---------------------------------------------------------------------------
// Kernel 1: proj via HMMA bf16x3; epilogue writes Apack = [hi|lo|hi] of proj.
// A = inputs-pack [hi|hi|lo], B = W-pack [hi|lo|hi]. grid (2, 64).
// ---------------------------------------------------------------------------
__global__ __launch_bounds__(256)
void proj_hmma(void)
{
    __shared__ __align__(128) char smem[2 * STAGEB];
    const int tid = threadIdx.x;
    const int rowBase = blockIdx.y * 128;
    const int colBase = blockIdx.x * 128;

    float acc[4][4][4];
    #pragma unroll
    for (int i = 0; i < 4; i++)
        #pragma unroll
        for (int j = 0; j < 4; j++)
            #pragma unroll
            for (int v = 0; v < 4; v++) acc[i][j][v] = 0.f;

    hmma_mainloop((const char*)(g_Bpack + (size_t)rowBase * KP),
                  (const char*)(g_Wpack + (size_t)colBase * KP),
                  smem, acc, tid);

    const int w = tid >> 5, l = tid & 31;
    const int mw = w >> 2, nw = w & 3;
    const int lq = l >> 2, lrm = l & 3;

    #pragma unroll
    for (int i = 0; i < 4; i++) {
        #pragma unroll
        for (int half = 0; half < 2; half++) {
            int row = rowBase + mw * 64 + i * 16 + lq + 8 * half;
            size_t base = (size_t)row * KP;
            #pragma unroll
            for (int j = 0; j < 4; j++) {
                int col = colBase + nw * 32 + j * 8 + lrm * 2;
                float x0 = acc[i][j][half * 2 + 0];
                float x1 = acc[i][j][half * 2 + 1];
                __nv_bfloat16 h0 = __float2bfloat16(x0);
                __nv_bfloat16 l0 = __float2bfloat16(x0 - __bfloat162float(h0));
                __nv_bfloat16 h1 = __float2bfloat16(x1);
                __nv_bfloat16 l1 = __float2bfloat16(x1 - __bfloat162float(h1));
                *(__nv_bfloat162*)(g_Apack + base + col)       = {h0, h1};
                *(__nv_bfloat162*)(g_Apack + base + 256 + col) = {l0, l1};
                *(__nv_bfloat162*)(g_Apack + base + 512 + col) = {h0, h1};
            }
        }
    }
}

// ---------------------------------------------------------------------------
// Kernel 2: att GEMM (identical mainloop), sigmoid epilogue + att store +
// per-warp w reduction. grid (16, 16, Bv).
// ---------------------------------------------------------------------------
__global__ __launch_bounds__(256)
void att_kernel(const float* __restrict__ mask, const float* __restrict__ aself,
                float* __restrict__ att_out)
{
    __shared__ __align__(128) char smem[2 * STAGEB];   // 40 KB

    const int tid = threadIdx.x;
    const int w = tid >> 5, l = tid & 31;
    const int mw = w >> 2, nw = w & 3;
    const int b = blockIdx.z;
    const int rowBase = blockIdx.y * 128;
    const int colBase = blockIdx.x * 128;

    float acc[4][4][4];
    #pragma unroll
    for (int i = 0; i < 4; i++)
        #pragma unroll
        for (int j = 0; j < 4; j++)
            #pragma unroll
            for (int v = 0; v < 4; v++) acc[i][j][v] = 0.f;

    hmma_mainloop((const char*)(g_Apack + (size_t)(b * ROWS + rowBase) * KP),
                  (const char*)(g_Bpack + (size_t)(b * ROWS + colBase) * KP),
                  smem, acc, tid);

    // ---- epilogue ----
    const int lq = l >> 2, lrm = l & 3;
    const int ii  = blockIdx.y * 2 + mw;
    const int jjg = blockIdx.x * 2 + (nw >> 1);

    float asv[4][2];
    #pragma unroll
    for (int i = 0; i < 4; i++)
        #pragma unroll
        for (int h = 0; h < 2; h++)
            asv[i][h] = aself[b * ROWS + rowBase + mw * 64 + i * 16 + lq + 8 * h];

    float mc[4][2];
    #pragma unroll
    for (int j = 0; j < 4; j++) {
        int tc = nw * 32 + j * 8 + lrm * 2;
        mc[j][0] = (1.0f - mask[b * ROWS + colBase + tc])     * NEG_BIG;
        mc[j][1] = (1.0f - mask[b * ROWS + colBase + tc + 1]) * NEG_BIG;
    }

    float wpart[4][2];
    #pragma unroll
    for (int j = 0; j < 4; j++) { wpart[j][0] = 0.f; wpart[j][1] = 0.f; }

    float* attB = att_out + (((size_t)((b * Cv + ii) * Cv + jjg)) << 12);

    #pragma unroll
    for (int i = 0; i < 4; i++) {
        int s_lo = i * 16 + lq;
        #pragma unroll
        for (int j = 0; j < 4; j++) {
            int tcol = (nw & 1) * 32 + j * 8 + lrm * 2;
            float a0 = fast_sigmoid(acc[i][j][0] + mc[j][0]);
            float a1 = fast_sigmoid(acc[i][j][1] + mc[j][1]);
            float a2 = fast_sigmoid(acc[i][j][2] + mc[j][0]);
            float a3 = fast_sigmoid(acc[i][j][3] + mc[j][1]);
            *(float2*)(attB + (size_t)s_lo * 64 + tcol)       = make_float2(a0, a1);
            *(float2*)(attB + (size_t)(s_lo + 8) * 64 + tcol) = make_float2(a2, a3);
            wpart[j][0] += a0 * asv[i][0] + a2 * asv[i][1];
            wpart[j][1] += a1 * asv[i][0] + a3 * asv[i][1];
        }
    }

    #pragma unroll
    for (int d = 4; d <= 16; d <<= 1)
        #pragma unroll
        for (int j = 0; j < 4; j++) {
            wpart[j][0] += __shfl_xor_sync(0xffffffffu, wpart[j][0], d);
            wpart[j][1] += __shfl_xor_sync(0xffffffffu, wpart[j][1], d);
        }
    if (lq == 0) {
        #pragma unroll
        for (int j = 0; j < 4; j++) {
            int tcol = (nw & 1) * 32 + j * 8 + lrm * 2;
            *(float2*)(g_w + ((size_t)((b * Cv + ii) * Cv + jjg)) * 64 + tcol)
                = make_float2(wpart[j][0], wpart[j][1]);
        }
    }
}

// ---------------------------------------------------------------------------
// Kernel 3: fused[b,i,j,h] = sum_t w[b,i,j,t] * inputs[b,j,t,h]
// grid (Cv, Bv, 4): each CTA handles 8 i's for one (b,j); single sync.
// ---------------------------------------------------------------------------
__global__ __launch_bounds__(256)
void fused_kernel(const float* __restrict__ inp, float* __restrict__ fused)
{
    const int j  = blockIdx.x;
    const int b  = blockIdx.y;
    const int i0 = blockIdx.z * 8;
    const int h  = threadIdx.x;

    const float* X = inp + (size_t)((b * Cv + j) * Sv) * Hv;
    float xc[64];
    #pragma unroll
    for (int t = 0; t < 64; t++) xc[t] = X[(size_t)t * Hv + h];

    __shared__ float sw[8][64];
    #pragma unroll
    for (int p = 0; p < 2; p++) {
        int idx = h + p * 256;           // 0..511
        int q = idx >> 6, t = idx & 63;
        sw[q][t] = g_w[((b * Cv + (i0 + q)) * Cv + j) * Sv + t];
    }
    __syncthreads();

    #pragma unroll
    for (int q = 0; q < 8; q++) {
        float acc = 0.f;
        #pragma unroll
        for (int t = 0; t < 64; t++) acc = fmaf(sw[q][t], xc[t], acc);
        fused[(size_t)((b * Cv + (i0 + q)) * Cv + j) * Hv + h] = acc;
    }
}

// ---------------------------------------------------------------------------
extern "C" void kernel_launch(void* const* d_in, const int* in_sizes, int n_in,
                              void* d_out, int out_size)
{
    const float* inputs = (const float*)d_in[0];   // [B,C,S,H]
    const float* mask   = (const float*)d_in[1];   // [B,C,S]
    const float* aself  = (const float*)d_in[2];   // [B,C,S]
    const float* W      = (const float*)d_in[3];   // [H,H]

    float* fused = (float*)d_out;                                  // [B,C,C,H]
    float* att   = (float*)d_out + (size_t)Bv * Cv * Cv * Hv;      // [B,C,C,S,S]

    pack_inputs<<<8192, 256>>>(inputs);
    pack_W<<<256, 256>>>(W);
    proj_hmma<<<dim3(2, 64, 1), 256>>>();
    att_kernel<<<dim3(16, 16, Bv), 256>>>(mask, aself, att);
    fused_kernel<<<dim3(Cv, Bv, 4), 256>>>(inputs, fused);
}

// round 9
// speedup vs baseline: 1.8927x; 1.0049x over previous
#include <cuda_runtime.h>
#include <cuda_bf16.h>
#include <math.h>
#include <stdint.h>

#define Bv 4
#define Cv 32
#define Sv 64
#define Hv 256
#define ROWS 2048
#define NEG_BIG (-1e10f)

#define KP 768            // packed K' = 3 * 256 bf16
#define KC 32             // bf16 per pipeline chunk
#define NCH 24            // KP / KC
#define SROW 80           // smem row stride in bytes (64B data + 16B pad)
#define TILEB (128 * SROW)        // 10240 B per operand tile
#define STAGEB (2 * TILEB)        // A + B per stage
#define NSTAGE 3
#define SMEM_DYN (NSTAGE * STAGEB)   // 61440 B

// ---- scratch (static device arrays) ----------------------------------------
__device__ __nv_bfloat16 g_Apack[(size_t)Bv * ROWS * KP];   // [hi | lo | hi] of proj
__device__ __nv_bfloat16 g_Bpack[(size_t)Bv * ROWS * KP];   // [hi | hi | lo] of inputs
__device__ __nv_bfloat16 g_Wpack[(size_t)Hv * KP];          // [hi | lo | hi] of W
__device__ float g_w[Bv * Cv * Cv * Sv];

// ---- helpers ---------------------------------------------------------------
__device__ __forceinline__ uint32_t s2u(const void* p) {
    uint32_t a;
    asm("{ .reg .u64 t; cvta.to.shared.u64 t, %1; cvt.u32.u64 %0, t; }"
        : "=r"(a) : "l"(p));
    return a;
}
__device__ __forceinline__ void cpasync16(uint32_t s, const void* g) {
    asm volatile("cp.async.cg.shared.global [%0], [%1], 16;" :: "r"(s), "l"(g));
}
__device__ __forceinline__ void ldsm4(uint32_t r[4], uint32_t addr) {
    asm volatile("ldmatrix.sync.aligned.m8n8.x4.shared.b16 {%0,%1,%2,%3}, [%4];"
        : "=r"(r[0]), "=r"(r[1]), "=r"(r[2]), "=r"(r[3]) : "r"(addr));
}
__device__ __forceinline__ void mma16816(float c[4], const uint32_t a[4],
                                         const uint32_t b[2]) {
    asm volatile(
        "mma.sync.aligned.m16n8k16.row.col.f32.bf16.bf16.f32 "
        "{%0,%1,%2,%3}, {%4,%5,%6,%7}, {%8,%9}, {%0,%1,%2,%3};"
        : "+f"(c[0]), "+f"(c[1]), "+f"(c[2]), "+f"(c[3])
        : "r"(a[0]), "r"(a[1]), "r"(a[2]), "r"(a[3]), "r"(b[0]), "r"(b[1]));
}

// ---- MUFU-free sigmoid (validated R4-R8) -----------------------------------
__device__ __forceinline__ float fast_sigmoid(float x) {
    x = fminf(30.0f, fmaxf(-30.0f, x));
    float t  = x * 1.4426950408889634f;
    float r  = t + 12582912.0f;
    float fi = r - 12582912.0f;
    float f  = t - fi;
    float p  = 1.3333558146428443e-3f;
    p = fmaf(p, f, 9.6181291076284772e-3f);
    p = fmaf(p, f, 5.5504108664821580e-2f);
    p = fmaf(p, f, 2.4022650695910072e-1f);
    p = fmaf(p, f, 6.9314718055994531e-1f);
    p = fmaf(p, f, 1.0f);
    int ei = __float_as_int(r) - 0x4B400000;
    float e = __int_as_float(__float_as_int(p) + (ei << 23));
    float d = 1.0f + e;
    float y = __int_as_float(0x7EF311C3 - __float_as_int(d));
    y = y * fmaf(-d, y, 2.0f);
    y = y * fmaf(-d, y, 2.0f);
    y = y * fmaf(-d, y, 2.0f);
    return e * y;
}

// ---------------------------------------------------------------------------
// Kernel 0a: pack inputs -> Bpack = [hi | hi | lo]
// ---------------------------------------------------------------------------
__global__ __launch_bounds__(256)
void pack_inputs(const float* __restrict__ inp)
{
    int idx = blockIdx.x * 256 + threadIdx.x;    // < Bv*ROWS*Hv = 2097152
    float x = inp[idx];
    __nv_bfloat16 hi = __float2bfloat16(x);
    __nv_bfloat16 lo = __float2bfloat16(x - __bfloat162float(hi));
    int row = idx >> 8, k = idx & 255;
    size_t base = (size_t)row * KP;
    g_Bpack[base + k]       = hi;
    g_Bpack[base + 256 + k] = hi;
    g_Bpack[base + 512 + k] = lo;
}

// ---------------------------------------------------------------------------
// Kernel 0b: pack W -> Wpack = [hi | lo | hi]
// ---------------------------------------------------------------------------
__global__ __launch_bounds__(256)
void pack_W(const float* __restrict__ W)
{
    int idx = blockIdx.x * 256 + threadIdx.x;    // < 65536
    float x = W[idx];
    __nv_bfloat16 hi = __float2bfloat16(x);
    __nv_bfloat16 lo = __float2bfloat16(x - __bfloat162float(hi));
    int row = idx >> 8, k = idx & 255;
    size_t base = (size_t)row * KP;
    g_Wpack[base + k]       = hi;
    g_Wpack[base + 256 + k] = lo;
    g_Wpack[base + 512 + k] = hi;
}

// ---------------------------------------------------------------------------
// Shared HMMA mainloop: 128x128 tile, K'=768, cp.async 3-stage pipeline,
// ONE __syncthreads per chunk. Warp grid 2(M) x 4(N).
// Safety: issue of chunk c+2 targets stage (c+2)%3 == (c-1)%3, the stage
// consumed at iteration c-1; the barrier at iteration c guarantees all warps
// finished that compute before any cp.async overwrites it.
// ---------------------------------------------------------------------------
__device__ __forceinline__ void hmma_mainloop(
    const char* __restrict__ Ag, const char* __restrict__ Bg,
    char* smem, float acc[4][4][4], int tid)
{
    const int w = tid >> 5, l = tid & 31;
    const int mw = w >> 2, nw = w & 3;
    const uint32_t sb = s2u(smem);

    const int r0 = tid >> 2;
    const int c0 = (tid & 3) * 16;

    const int q = l >> 3, lr = l & 7;
    const uint32_t aoff = (uint32_t)((mw * 64 + (q & 1) * 8 + lr) * SROW + (q >> 1) * 16);
    const uint32_t boff = (uint32_t)(TILEB + (nw * 32 + (q >> 1) * 8 + lr) * SROW + (q & 1) * 16);

    auto issue = [&](int c, int stage) {
        uint32_t st = sb + stage * STAGEB;
        size_t gk = (size_t)c * (KC * 2);
        #pragma unroll
        for (int p = 0; p < 2; p++) {
            int rr = r0 + p * 64;
            cpasync16(st + rr * SROW + c0,         Ag + (size_t)rr * (KP * 2) + gk + c0);
            cpasync16(st + TILEB + rr * SROW + c0, Bg + (size_t)rr * (KP * 2) + gk + c0);
        }
        asm volatile("cp.async.commit_group;" ::: "memory");
    };

    issue(0, 0);
    issue(1, 1);

    int s_comp = 0;      // stage of chunk c
    int s_iss  = 2;      // stage for chunk c+2

    for (int c = 0; c < NCH; c++) {
        if (c + 1 >= NCH) asm volatile("cp.async.wait_group 0;" ::: "memory");
        else              asm volatile("cp.async.wait_group 1;" ::: "memory");
        __syncthreads();

        if (c + 2 < NCH) issue(c + 2, s_iss);

        uint32_t st = sb + s_comp * STAGEB;
        #pragma unroll
        for (int ks = 0; ks < 2; ks++) {
            uint32_t a_[4][4];
            uint32_t b_[4][2];
            #pragma unroll
            for (int i = 0; i < 4; i++)
                ldsm4(a_[i], st + aoff + i * 16 * SROW + ks * 32);
            #pragma unroll
            for (int jj = 0; jj < 2; jj++) {
                uint32_t t4[4];
                ldsm4(t4, st + boff + jj * 16 * SROW + ks * 32);
                b_[jj * 2][0]     = t4[0]; b_[jj * 2][1]     = t4[1];
                b_[jj * 2 + 1][0] = t4[2]; b_[jj * 2 + 1][1] = t4[3];
            }
            #pragma unroll
            for (int i = 0; i < 4; i++)
                #pragma unroll
                for (int j = 0; j < 4; j++)
                    mma16816(acc[i][j], a_[i], b_[j]);
        }
        s_comp = (s_comp == 2) ? 0 : s_comp + 1;
        s_iss  = (s_iss  == 2) ? 0 : s_iss  + 1;
    }
}

// ---------------------------------------------------------------------------
// Kernel 1: proj via HMMA bf16x3; epilogue writes Apack = [hi|lo|hi] of proj.
// ---------------------------------------------------------------------------
__global__ __launch_bounds__(256)
void proj_hmma(void)
{
    extern __shared__ __align__(128) char smem[];
    const int tid = threadIdx.x;
    const int rowBase = blockIdx.y * 128;
    const int colBase = blockIdx.x * 128;

    float acc[4][4][4];
    #pragma unroll
    for (int i = 0; i < 4; i++)
        #pragma unroll
        for (int j = 0; j < 4; j++)
            #pragma unroll
            for (int v = 0; v < 4; v++) acc[i][j][v] = 0.f;

    hmma_mainloop((const char*)(g_Bpack + (size_t)rowBase * KP),
                  (const char*)(g_Wpack + (size_t)colBase * KP),
                  smem, acc, tid);

    const int w = tid >> 5, l = tid & 31;
    const int mw = w >> 2, nw = w & 3;
    const int lq = l >> 2, lrm = l & 3;

    #pragma unroll
    for (int i = 0; i < 4; i++) {
        #pragma unroll
        for (int half = 0; half < 2; half++) {
            int row = rowBase + mw * 64 + i * 16 + lq + 8 * half;
            size_t base = (size_t)row * KP;
            #pragma unroll
            for (int j = 0; j < 4; j++) {
                int col = colBase + nw * 32 + j * 8 + lrm * 2;
                float x0 = acc[i][j][half * 2 + 0];
                float x1 = acc[i][j][half * 2 + 1];
                __nv_bfloat16 h0 = __float2bfloat16(x0);
                __nv_bfloat16 l0 = __float2bfloat16(x0 - __bfloat162float(h0));
                __nv_bfloat16 h1 = __float2bfloat16(x1);
                __nv_bfloat16 l1 = __float2bfloat16(x1 - __bfloat162float(h1));
                *(__nv_bfloat162*)(g_Apack + base + col)       = {h0, h1};
                *(__nv_bfloat162*)(g_Apack + base + 256 + col) = {l0, l1};
                *(__nv_bfloat162*)(g_Apack + base + 512 + col) = {h0, h1};
            }
        }
    }
}

// ---------------------------------------------------------------------------
// Kernel 2: att GEMM, sigmoid epilogue + att store + per-warp w reduction.
// ---------------------------------------------------------------------------
__global__ __launch_bounds__(256)
void att_kernel(const float* __restrict__ mask, const float* __restrict__ aself,
                float* __restrict__ att_out)
{
    extern __shared__ __align__(128) char smem[];

    const int tid = threadIdx.x;
    const int w = tid >> 5, l = tid & 31;
    const int mw = w >> 2, nw = w & 3;
    const int b = blockIdx.z;
    const int rowBase = blockIdx.y * 128;
    const int colBase = blockIdx.x * 128;

    float acc[4][4][4];
    #pragma unroll
    for (int i = 0; i < 4; i++)
        #pragma unroll
        for (int j = 0; j < 4; j++)
            #pragma unroll
            for (int v = 0; v < 4; v++) acc[i][j][v] = 0.f;

    hmma_mainloop((const char*)(g_Apack + (size_t)(b * ROWS + rowBase) * KP),
                  (const char*)(g_Bpack + (size_t)(b * ROWS + colBase) * KP),
                  smem, acc, tid);

    // ---- epilogue ----
    const int lq = l >> 2, lrm = l & 3;
    const int ii  = blockIdx.y * 2 + mw;
    const int jjg = blockIdx.x * 2 + (nw >> 1);

    float asv[4][2];
    #pragma unroll
    for (int i = 0; i < 4; i++)
        #pragma unroll
        for (int h = 0; h < 2; h++)
            asv[i][h] = aself[b * ROWS + rowBase + mw * 64 + i * 16 + lq + 8 * h];

    float mc[4][2];
    #pragma unroll
    for (int j = 0; j < 4; j++) {
        int tc = nw * 32 + j * 8 + lrm * 2;
        mc[j][0] = (1.0f - mask[b * ROWS + colBase + tc])     * NEG_BIG;
        mc[j][1] = (1.0f - mask[b * ROWS + colBase + tc + 1]) * NEG_BIG;
    }

    float wpart[4][2];
    #pragma unroll
    for (int j = 0; j < 4; j++) { wpart[j][0] = 0.f; wpart[j][1] = 0.f; }

    float* attB = att_out + (((size_t)((b * Cv + ii) * Cv + jjg)) << 12);

    #pragma unroll
    for (int i = 0; i < 4; i++) {
        int s_lo = i * 16 + lq;
        #pragma unroll
        for (int j = 0; j < 4; j++) {
            int tcol = (nw & 1) * 32 + j * 8 + lrm * 2;
            float a0 = fast_sigmoid(acc[i][j][0] + mc[j][0]);
            float a1 = fast_sigmoid(acc[i][j][1] + mc[j][1]);
            float a2 = fast_sigmoid(acc[i][j][2] + mc[j][0]);
            float a3 = fast_sigmoid(acc[i][j][3] + mc[j][1]);
            *(float2*)(attB + (size_t)s_lo * 64 + tcol)       = make_float2(a0, a1);
            *(float2*)(attB + (size_t)(s_lo + 8) * 64 + tcol) = make_float2(a2, a3);
            wpart[j][0] += a0 * asv[i][0] + a2 * asv[i][1];
            wpart[j][1] += a1 * asv[i][0] + a3 * asv[i][1];
        }
    }

    #pragma unroll
    for (int d = 4; d <= 16; d <<= 1)
        #pragma unroll
        for (int j = 0; j < 4; j++) {
            wpart[j][0] += __shfl_xor_sync(0xffffffffu, wpart[j][0], d);
            wpart[j][1] += __shfl_xor_sync(0xffffffffu, wpart[j][1], d);
        }
    if (lq == 0) {
        #pragma unroll
        for (int j = 0; j < 4; j++) {
            int tcol = (nw & 1) * 32 + j * 8 + lrm * 2;
            *(float2*)(g_w + ((size_t)((b * Cv + ii) * Cv + jjg)) * 64 + tcol)
                = make_float2(wpart[j][0], wpart[j][1]);
        }
    }
}

// ---------------------------------------------------------------------------
// Kernel 3: fused[b,i,j,h] = sum_t w[b,i,j,t] * inputs[b,j,t,h]
// ---------------------------------------------------------------------------
__global__ __launch_bounds__(256)
void fused_kernel(const float* __restrict__ inp, float* __restrict__ fused)
{
    const int j  = blockIdx.x;
    const int b  = blockIdx.y;
    const int i0 = blockIdx.z * 8;
    const int h  = threadIdx.x;

    const float* X = inp + (size_t)((b * Cv + j) * Sv) * Hv;
    float xc[64];
    #pragma unroll
    for (int t = 0; t < 64; t++) xc[t] = X[(size_t)t * Hv + h];

    __shared__ float sw[8][64];
    #pragma unroll
    for (int p = 0; p < 2; p++) {
        int idx = h + p * 256;           // 0..511
        int qq = idx >> 6, t = idx & 63;
        sw[qq][t] = g_w[((b * Cv + (i0 + qq)) * Cv + j) * Sv + t];
    }
    __syncthreads();

    #pragma unroll
    for (int qq = 0; qq < 8; qq++) {
        float acc = 0.f;
        #pragma unroll
        for (int t = 0; t < 64; t++) acc = fmaf(sw[qq][t], xc[t], acc);
        fused[(size_t)((b * Cv + (i0 + qq)) * Cv + j) * Hv + h] = acc;
    }
}

// ---------------------------------------------------------------------------
extern "C" void kernel_launch(void* const* d_in, const int* in_sizes, int n_in,
                              void* d_out, int out_size)
{
    const float* inputs = (const float*)d_in[0];   // [B,C,S,H]
    const float* mask   = (const float*)d_in[1];   // [B,C,S]
    const float* aself  = (const float*)d_in[2];   // [B,C,S]
    const float* W      = (const float*)d_in[3];   // [H,H]

    float* fused = (float*)d_out;                                  // [B,C,C,H]
    float* att   = (float*)d_out + (size_t)Bv * Cv * Cv * Hv;      // [B,C,C,S,S]

    cudaFuncSetAttribute(proj_hmma, cudaFuncAttributeMaxDynamicSharedMemorySize,
                         SMEM_DYN);
    cudaFuncSetAttribute(att_kernel, cudaFuncAttributeMaxDynamicSharedMemorySize,
                         SMEM_DYN);

    pack_inputs<<<8192, 256>>>(inputs);
    pack_W<<<256, 256>>>(W);
    proj_hmma<<<dim3(2, 64, 1), 256, SMEM_DYN>>>();
    att_kernel<<<dim3(16, 16, Bv), 256, SMEM_DYN>>>(mask, aself, att);
    fused_kernel<<<dim3(Cv, Bv, 4), 256>>>(inputs, fused);
}

// round 10
// speedup vs baseline: 2.1988x; 1.1617x over previous
#include <cuda_runtime.h>
#include <cuda_bf16.h>
#include <math.h>
#include <stdint.h>

#define Bv 4
#define Cv 32
#define Sv 64
#define Hv 256
#define ROWS 2048
#define NEG_BIG (-1e10f)

#define KP 768            // packed K' = 3 * 256 bf16
#define KC 32             // bf16 per pipeline chunk
#define NCH 24            // KP / KC
#define SROW 80           // smem row stride in bytes (64B data + 16B pad)
#define TILEB (128 * SROW)        // 10240 B per operand tile
#define STAGEB (2 * TILEB)        // A + B per stage
#define NSTAGE 4
#define SMEM_DYN (NSTAGE * STAGEB)   // 81920 B

// ---- scratch (static device arrays) ----------------------------------------
__device__ __nv_bfloat16 g_Apack[(size_t)Bv * ROWS * KP];   // [hi | lo | hi] of proj
__device__ __nv_bfloat16 g_Bpack[(size_t)Bv * ROWS * KP];   // [hi | hi | lo] of inputs
__device__ __nv_bfloat16 g_Wpack[(size_t)Hv * KP];          // [hi | lo | hi] of W
__device__ float g_w[Bv * Cv * Cv * Sv];

// ---- helpers ---------------------------------------------------------------
__device__ __forceinline__ uint32_t s2u(const void* p) {
    uint32_t a;
    asm("{ .reg .u64 t; cvta.to.shared.u64 t, %1; cvt.u32.u64 %0, t; }"
        : "=r"(a) : "l"(p));
    return a;
}
__device__ __forceinline__ void cpasync16(uint32_t s, const void* g) {
    asm volatile("cp.async.cg.shared.global [%0], [%1], 16;" :: "r"(s), "l"(g));
}
__device__ __forceinline__ void ldsm4(uint32_t r[4], uint32_t addr) {
    asm volatile("ldmatrix.sync.aligned.m8n8.x4.shared.b16 {%0,%1,%2,%3}, [%4];"
        : "=r"(r[0]), "=r"(r[1]), "=r"(r[2]), "=r"(r[3]) : "r"(addr));
}
__device__ __forceinline__ void mma16816(float c[4], const uint32_t a[4],
                                         const uint32_t b[2]) {
    asm volatile(
        "mma.sync.aligned.m16n8k16.row.col.f32.bf16.bf16.f32 "
        "{%0,%1,%2,%3}, {%4,%5,%6,%7}, {%8,%9}, {%0,%1,%2,%3};"
        : "+f"(c[0]), "+f"(c[1]), "+f"(c[2]), "+f"(c[3])
        : "r"(a[0]), "r"(a[1]), "r"(a[2]), "r"(a[3]), "r"(b[0]), "r"(b[1]));
}

// ---- MUFU-free sigmoid (validated R4-R9) -----------------------------------
__device__ __forceinline__ float fast_sigmoid(float x) {
    x = fminf(30.0f, fmaxf(-30.0f, x));
    float t  = x * 1.4426950408889634f;
    float r  = t + 12582912.0f;
    float fi = r - 12582912.0f;
    float f  = t - fi;
    float p  = 1.3333558146428443e-3f;
    p = fmaf(p, f, 9.6181291076284772e-3f);
    p = fmaf(p, f, 5.5504108664821580e-2f);
    p = fmaf(p, f, 2.4022650695910072e-1f);
    p = fmaf(p, f, 6.9314718055994531e-1f);
    p = fmaf(p, f, 1.0f);
    int ei = __float_as_int(r) - 0x4B400000;
    float e = __int_as_float(__float_as_int(p) + (ei << 23));
    float d = 1.0f + e;
    float y = __int_as_float(0x7EF311C3 - __float_as_int(d));
    y = y * fmaf(-d, y, 2.0f);
    y = y * fmaf(-d, y, 2.0f);
    y = y * fmaf(-d, y, 2.0f);
    return e * y;
}

// ---------------------------------------------------------------------------
// Kernel 0a: pack inputs -> Bpack = [hi | hi | lo]
// ---------------------------------------------------------------------------
__global__ __launch_bounds__(256)
void pack_inputs(const float* __restrict__ inp)
{
    int idx = blockIdx.x * 256 + threadIdx.x;    // < Bv*ROWS*Hv = 2097152
    float x = inp[idx];
    __nv_bfloat16 hi = __float2bfloat16(x);
    __nv_bfloat16 lo = __float2bfloat16(x - __bfloat162float(hi));
    int row = idx >> 8, k = idx & 255;
    size_t base = (size_t)row * KP;
    g_Bpack[base + k]       = hi;
    g_Bpack[base + 256 + k] = hi;
    g_Bpack[base + 512 + k] = lo;
}

// ---------------------------------------------------------------------------
// Kernel 0b: pack W -> Wpack = [hi | lo | hi]
// ---------------------------------------------------------------------------
__global__ __launch_bounds__(256)
void pack_W(const float* __restrict__ W)
{
    int idx = blockIdx.x * 256 + threadIdx.x;    // < 65536
    float x = W[idx];
    __nv_bfloat16 hi = __float2bfloat16(x);
    __nv_bfloat16 lo = __float2bfloat16(x - __bfloat162float(hi));
    int row = idx >> 8, k = idx & 255;
    size_t base = (size_t)row * KP;
    g_Wpack[base + k]       = hi;
    g_Wpack[base + 256 + k] = lo;
    g_Wpack[base + 512 + k] = hi;
}

// ---------------------------------------------------------------------------
// Shared HMMA mainloop: 128x128 tile, K'=768, 4-stage cp.async ring, single
// barrier per chunk, register double-buffered fragments (ks-level prefetch
// crossing chunk boundaries). Warp grid 2(M) x 4(N).
//
// Group accounting: every iteration commits exactly one group (empty commit
// near the tail), so after the wait at iteration c the groups 0..c+1 are
// complete -> chunk c+1's data is in smem before its fragments are loaded.
// Stage reuse: issue at iter c targets stage (c+3)%4 == (c-1)%4, whose last
// reader finished before the iter c-1 barrier.
// ---------------------------------------------------------------------------
__device__ __forceinline__ void hmma_mainloop(
    const char* __restrict__ Ag, const char* __restrict__ Bg,
    char* smem, float acc[4][4][4], int tid)
{
    const int w = tid >> 5, l = tid & 31;
    const int mw = w >> 2, nw = w & 3;
    const uint32_t sb = s2u(smem);

    const int r0 = tid >> 2;
    const int c0 = (tid & 3) * 16;

    const int q = l >> 3, lr = l & 7;
    const uint32_t aoff = (uint32_t)((mw * 64 + (q & 1) * 8 + lr) * SROW + (q >> 1) * 16);
    const uint32_t boff = (uint32_t)(TILEB + (nw * 32 + (q >> 1) * 8 + lr) * SROW + (q & 1) * 16);

    auto issue = [&](int c) {
        if (c < NCH) {
            uint32_t st = sb + (c & 3) * STAGEB;
            size_t gk = (size_t)c * (KC * 2);
            #pragma unroll
            for (int p = 0; p < 2; p++) {
                int rr = r0 + p * 64;
                cpasync16(st + rr * SROW + c0,         Ag + (size_t)rr * (KP * 2) + gk + c0);
                cpasync16(st + TILEB + rr * SROW + c0, Bg + (size_t)rr * (KP * 2) + gk + c0);
            }
        }
        asm volatile("cp.async.commit_group;" ::: "memory");
    };

    uint32_t a0[4][4], b0[4][2], a1[4][4], b1[4][2];

    auto ldA = [&](uint32_t st, int ks, uint32_t a_[4][4]) {
        #pragma unroll
        for (int i = 0; i < 4; i++)
            ldsm4(a_[i], st + aoff + i * 16 * SROW + ks * 32);
    };
    auto ldB = [&](uint32_t st, int ks, uint32_t b_[4][2]) {
        #pragma unroll
        for (int jj = 0; jj < 2; jj++) {
            uint32_t t4[4];
            ldsm4(t4, st + boff + jj * 16 * SROW + ks * 32);
            b_[jj * 2][0]     = t4[0]; b_[jj * 2][1]     = t4[1];
            b_[jj * 2 + 1][0] = t4[2]; b_[jj * 2 + 1][1] = t4[3];
        }
    };
    auto domma = [&](uint32_t a_[4][4], uint32_t b_[4][2]) {
        #pragma unroll
        for (int i = 0; i < 4; i++)
            #pragma unroll
            for (int j = 0; j < 4; j++)
                mma16816(acc[i][j], a_[i], b_[j]);
    };

    issue(0); issue(1); issue(2);
    asm volatile("cp.async.wait_group 2;" ::: "memory");
    __syncthreads();
    ldA(sb, 0, a0); ldB(sb, 0, b0);          // chunk 0, ks 0

    for (int c = 0; c < NCH; c++) {
        uint32_t stc = sb + (c & 3) * STAGEB;
        issue(c + 3);                          // into stage (c-1)%4 (free)
        ldA(stc, 1, a1); ldB(stc, 1, b1);      // chunk c, ks 1 (prefetch)
        domma(a0, b0);                         // chunk c, ks 0
        if (c + 1 < NCH) {
            asm volatile("cp.async.wait_group 2;" ::: "memory");
            __syncthreads();
            uint32_t stn = sb + ((c + 1) & 3) * STAGEB;
            ldA(stn, 0, a0); ldB(stn, 0, b0);  // chunk c+1, ks 0 (prefetch)
        }
        domma(a1, b1);                         // chunk c, ks 1
    }
}

// ---------------------------------------------------------------------------
// Kernel 1: proj via HMMA bf16x3; epilogue writes Apack = [hi|lo|hi] of proj.
// ---------------------------------------------------------------------------
__global__ __launch_bounds__(256, 2)
void proj_hmma(void)
{
    extern __shared__ __align__(128) char smem[];
    const int tid = threadIdx.x;
    const int rowBase = blockIdx.y * 128;
    const int colBase = blockIdx.x * 128;

    float acc[4][4][4];
    #pragma unroll
    for (int i = 0; i < 4; i++)
        #pragma unroll
        for (int j = 0; j < 4; j++)
            #pragma unroll
            for (int v = 0; v < 4; v++) acc[i][j][v] = 0.f;

    hmma_mainloop((const char*)(g_Bpack + (size_t)rowBase * KP),
                  (const char*)(g_Wpack + (size_t)colBase * KP),
                  smem, acc, tid);

    const int w = tid >> 5, l = tid & 31;
    const int mw = w >> 2, nw = w & 3;
    const int lq = l >> 2, lrm = l & 3;

    #pragma unroll
    for (int i = 0; i < 4; i++) {
        #pragma unroll
        for (int half = 0; half < 2; half++) {
            int row = rowBase + mw * 64 + i * 16 + lq + 8 * half;
            size_t base = (size_t)row * KP;
            #pragma unroll
            for (int j = 0; j < 4; j++) {
                int col = colBase + nw * 32 + j * 8 + lrm * 2;
                float x0 = acc[i][j][half * 2 + 0];
                float x1 = acc[i][j][half * 2 + 1];
                __nv_bfloat16 h0 = __float2bfloat16(x0);
                __nv_bfloat16 l0 = __float2bfloat16(x0 - __bfloat162float(h0));
                __nv_bfloat16 h1 = __float2bfloat16(x1);
                __nv_bfloat16 l1 = __float2bfloat16(x1 - __bfloat162float(h1));
                *(__nv_bfloat162*)(g_Apack + base + col)       = {h0, h1};
                *(__nv_bfloat162*)(g_Apack + base + 256 + col) = {l0, l1};
                *(__nv_bfloat162*)(g_Apack + base + 512 + col) = {h0, h1};
            }
        }
    }
}

// ---------------------------------------------------------------------------
// Kernel 2: att GEMM, sigmoid epilogue + att store + per-warp w reduction.
// ---------------------------------------------------------------------------
__global__ __launch_bounds__(256, 2)
void att_kernel(const float* __restrict__ mask, const float* __restrict__ aself,
                float* __restrict__ att_out)
{
    extern __shared__ __align__(128) char smem[];

    const int tid = threadIdx.x;
    const int w = tid >> 5, l = tid & 31;
    const int mw = w >> 2, nw = w & 3;
    const int b = blockIdx.z;
    const int rowBase = blockIdx.y * 128;
    const int colBase = blockIdx.x * 128;

    float acc[4][4][4];
    #pragma unroll
    for (int i = 0; i < 4; i++)
        #pragma unroll
        for (int j = 0; j < 4; j++)
            #pragma unroll
            for (int v = 0; v < 4; v++) acc[i][j][v] = 0.f;

    hmma_mainloop((const char*)(g_Apack + (size_t)(b * ROWS + rowBase) * KP),
                  (const char*)(g_Bpack + (size_t)(b * ROWS + colBase) * KP),
                  smem, acc, tid);

    // ---- epilogue ----
    const int lq = l >> 2, lrm = l & 3;
    const int ii  = blockIdx.y * 2 + mw;
    const int jjg = blockIdx.x * 2 + (nw >> 1);

    float asv[4][2];
    #pragma unroll
    for (int i = 0; i < 4; i++)
        #pragma unroll
        for (int h = 0; h < 2; h++)
            asv[i][h] = aself[b * ROWS + rowBase + mw * 64 + i * 16 + lq + 8 * h];

    float mc[4][2];
    #pragma unroll
    for (int j = 0; j < 4; j++) {
        int tc = nw * 32 + j * 8 + lrm * 2;
        mc[j][0] = (1.0f - mask[b * ROWS + colBase + tc])     * NEG_BIG;
        mc[j][1] = (1.0f - mask[b * ROWS + colBase + tc + 1]) * NEG_BIG;
    }

    float wpart[4][2];
    #pragma unroll
    for (int j = 0; j < 4; j++) { wpart[j][0] = 0.f; wpart[j][1] = 0.f; }

    float* attB = att_out + (((size_t)((b * Cv + ii) * Cv + jjg)) << 12);

    #pragma unroll
    for (int i = 0; i < 4; i++) {
        int s_lo = i * 16 + lq;
        #pragma unroll
        for (int j = 0; j < 4; j++) {
            int tcol = (nw & 1) * 32 + j * 8 + lrm * 2;
            float a0 = fast_sigmoid(acc[i][j][0] + mc[j][0]);
            float a1 = fast_sigmoid(acc[i][j][1] + mc[j][1]);
            float a2 = fast_sigmoid(acc[i][j][2] + mc[j][0]);
            float a3 = fast_sigmoid(acc[i][j][3] + mc[j][1]);
            *(float2*)(attB + (size_t)s_lo * 64 + tcol)       = make_float2(a0, a1);
            *(float2*)(attB + (size_t)(s_lo + 8) * 64 + tcol) = make_float2(a2, a3);
            wpart[j][0] += a0 * asv[i][0] + a2 * asv[i][1];
            wpart[j][1] += a1 * asv[i][0] + a3 * asv[i][1];
        }
    }

    #pragma unroll
    for (int d = 4; d <= 16; d <<= 1)
        #pragma unroll
        for (int j = 0; j < 4; j++) {
            wpart[j][0] += __shfl_xor_sync(0xffffffffu, wpart[j][0], d);
            wpart[j][1] += __shfl_xor_sync(0xffffffffu, wpart[j][1], d);
        }
    if (lq == 0) {
        #pragma unroll
        for (int j = 0; j < 4; j++) {
            int tcol = (nw & 1) * 32 + j * 8 + lrm * 2;
            *(float2*)(g_w + ((size_t)((b * Cv + ii) * Cv + jjg)) * 64 + tcol)
                = make_float2(wpart[j][0], wpart[j][1]);
        }
    }
}

// ---------------------------------------------------------------------------
// Kernel 3: fused[b,i,j,h] = sum_t w[b,i,j,t] * inputs[b,j,t,h]
// ---------------------------------------------------------------------------
__global__ __launch_bounds__(256)
void fused_kernel(const float* __restrict__ inp, float* __restrict__ fused)
{
    const int j  = blockIdx.x;
    const int b  = blockIdx.y;
    const int i0 = blockIdx.z * 8;
    const int h  = threadIdx.x;

    const float* X = inp + (size_t)((b * Cv + j) * Sv) * Hv;
    float xc[64];
    #pragma unroll
    for (int t = 0; t < 64; t++) xc[t] = X[(size_t)t * Hv + h];

    __shared__ float sw[8][64];
    #pragma unroll
    for (int p = 0; p < 2; p++) {
        int idx = h + p * 256;           // 0..511
        int qq = idx >> 6, t = idx & 63;
        sw[qq][t] = g_w[((b * Cv + (i0 + qq)) * Cv + j) * Sv + t];
    }
    __syncthreads();

    #pragma unroll
    for (int qq = 0; qq < 8; qq++) {
        float acc = 0.f;
        #pragma unroll
        for (int t = 0; t < 64; t++) acc = fmaf(sw[qq][t], xc[t], acc);
        fused[(size_t)((b * Cv + (i0 + qq)) * Cv + j) * Hv + h] = acc;
    }
}

// ---------------------------------------------------------------------------
extern "C" void kernel_launch(void* const* d_in, const int* in_sizes, int n_in,
                              void* d_out, int out_size)
{
    const float* inputs = (const float*)d_in[0];   // [B,C,S,H]
    const float* mask   = (const float*)d_in[1];   // [B,C,S]
    const float* aself  = (const float*)d_in[2];   // [B,C,S]
    const float* W      = (const float*)d_in[3];   // [H,H]

    float* fused = (float*)d_out;                                  // [B,C,C,H]
    float* att   = (float*)d_out + (size_t)Bv * Cv * Cv * Hv;      // [B,C,C,S,S]

    cudaFuncSetAttribute(proj_hmma, cudaFuncAttributeMaxDynamicSharedMemorySize,
                         SMEM_DYN);
    cudaFuncSetAttribute(att_kernel, cudaFuncAttributeMaxDynamicSharedMemorySize,
                         SMEM_DYN);

    pack_inputs<<<8192, 256>>>(inputs);
    pack_W<<<256, 256>>>(W);
    proj_hmma<<<dim3(2, 64, 1), 256, SMEM_DYN>>>();
    att_kernel<<<dim3(16, 16, Bv), 256, SMEM_DYN>>>(mask, aself, att);
    fused_kernel<<<dim3(Cv, Bv, 4), 256>>>(inputs, fused);
}

// round 11
// speedup vs baseline: 2.2382x; 1.0179x over previous
#include <cuda_runtime.h>
#include <cuda_bf16.h>
#include <math.h>
#include <stdint.h>

#define Bv 4
#define Cv 32
#define Sv 64
#define Hv 256
#define ROWS 2048
#define NEG_BIG (-1e10f)

#define KP 768            // packed K' = 3 * 256 bf16
#define KC 64             // bf16 per pipeline chunk (128B per row)
#define NCH 12            // KP / KC
#define SROW 144          // smem row stride in bytes (128B data + 16B pad)
#define TILEB (128 * SROW)        // 18432 B per operand tile
#define STAGEB (2 * TILEB)        // A + B per stage
#define NSTAGE 3
#define SMEM_DYN (NSTAGE * STAGEB)   // 110592 B

// ---- scratch (static device arrays) ----------------------------------------
__device__ __nv_bfloat16 g_Apack[(size_t)Bv * ROWS * KP];   // [hi | lo | hi] of proj
__device__ __nv_bfloat16 g_Bpack[(size_t)Bv * ROWS * KP];   // [hi | hi | lo] of inputs
__device__ __nv_bfloat16 g_Wpack[(size_t)Hv * KP];          // [hi | lo | hi] of W
__device__ float g_w[Bv * Cv * Cv * Sv];

// ---- helpers ---------------------------------------------------------------
__device__ __forceinline__ uint32_t s2u(const void* p) {
    uint32_t a;
    asm("{ .reg .u64 t; cvta.to.shared.u64 t, %1; cvt.u32.u64 %0, t; }"
        : "=r"(a) : "l"(p));
    return a;
}
__device__ __forceinline__ void cpasync16(uint32_t s, const void* g) {
    asm volatile("cp.async.cg.shared.global [%0], [%1], 16;" :: "r"(s), "l"(g));
}
__device__ __forceinline__ void ldsm4(uint32_t r[4], uint32_t addr) {
    asm volatile("ldmatrix.sync.aligned.m8n8.x4.shared.b16 {%0,%1,%2,%3}, [%4];"
        : "=r"(r[0]), "=r"(r[1]), "=r"(r[2]), "=r"(r[3]) : "r"(addr));
}
__device__ __forceinline__ void mma16816(float c[4], const uint32_t a[4],
                                         const uint32_t b[2]) {
    asm volatile(
        "mma.sync.aligned.m16n8k16.row.col.f32.bf16.bf16.f32 "
        "{%0,%1,%2,%3}, {%4,%5,%6,%7}, {%8,%9}, {%0,%1,%2,%3};"
        : "+f"(c[0]), "+f"(c[1]), "+f"(c[2]), "+f"(c[3])
        : "r"(a[0]), "r"(a[1]), "r"(a[2]), "r"(a[3]), "r"(b[0]), "r"(b[1]));
}

// ---- MUFU-free sigmoid (validated R4-R10) ----------------------------------
__device__ __forceinline__ float fast_sigmoid(float x) {
    x = fminf(30.0f, fmaxf(-30.0f, x));
    float t  = x * 1.4426950408889634f;
    float r  = t + 12582912.0f;
    float fi = r - 12582912.0f;
    float f  = t - fi;
    float p  = 1.3333558146428443e-3f;
    p = fmaf(p, f, 9.6181291076284772e-3f);
    p = fmaf(p, f, 5.5504108664821580e-2f);
    p = fmaf(p, f, 2.4022650695910072e-1f);
    p = fmaf(p, f, 6.9314718055994531e-1f);
    p = fmaf(p, f, 1.0f);
    int ei = __float_as_int(r) - 0x4B400000;
    float e = __int_as_float(__float_as_int(p) + (ei << 23));
    float d = 1.0f + e;
    float y = __int_as_float(0x7EF311C3 - __float_as_int(d));
    y = y * fmaf(-d, y, 2.0f);
    y = y * fmaf(-d, y, 2.0f);
    y = y * fmaf(-d, y, 2.0f);
    return e * y;
}

// ---------------------------------------------------------------------------
// Kernel 0a: pack inputs -> Bpack = [hi | hi | lo]
// ---------------------------------------------------------------------------
__global__ __launch_bounds__(256)
void pack_inputs(const float* __restrict__ inp)
{
    int idx = blockIdx.x * 256 + threadIdx.x;    // < Bv*ROWS*Hv = 2097152
    float x = inp[idx];
    __nv_bfloat16 hi = __float2bfloat16(x);
    __nv_bfloat16 lo = __float2bfloat16(x - __bfloat162float(hi));
    int row = idx >> 8, k = idx & 255;
    size_t base = (size_t)row * KP;
    g_Bpack[base + k]       = hi;
    g_Bpack[base + 256 + k] = hi;
    g_Bpack[base + 512 + k] = lo;
}

// ---------------------------------------------------------------------------
// Kernel 0b: pack W -> Wpack = [hi | lo | hi]
// ---------------------------------------------------------------------------
__global__ __launch_bounds__(256)
void pack_W(const float* __restrict__ W)
{
    int idx = blockIdx.x * 256 + threadIdx.x;    // < 65536
    float x = W[idx];
    __nv_bfloat16 hi = __float2bfloat16(x);
    __nv_bfloat16 lo = __float2bfloat16(x - __bfloat162float(hi));
    int row = idx >> 8, k = idx & 255;
    size_t base = (size_t)row * KP;
    g_Wpack[base + k]       = hi;
    g_Wpack[base + 256 + k] = lo;
    g_Wpack[base + 512 + k] = hi;
}

// ---------------------------------------------------------------------------
// Shared HMMA mainloop: 128x128 tile, K'=768, KC=64 chunks (4 ks-steps each),
// 3-stage cp.async ring, ONE barrier per chunk, register ping-pong fragments.
// Warp grid 2(M) x 4(N).
//
// Group accounting: one commit per chunk. At iter c's last ks, wait_group 1
// leaves only group c+2 possibly in flight -> chunk c+1 resident.
// Stage reuse: issue(c+2) writes stage (c+2)%3 == (c-1)%3; the barrier inside
// iter c-1's last ks-step ordered all reads of that stage before it.
// ---------------------------------------------------------------------------
__device__ __forceinline__ void hmma_mainloop(
    const char* __restrict__ Ag, const char* __restrict__ Bg,
    char* smem, float acc[4][4][4], int tid)
{
    const int w = tid >> 5, l = tid & 31;
    const int mw = w >> 2, nw = w & 3;
    const uint32_t sb = s2u(smem);

    const int q = l >> 3, lr = l & 7;
    const uint32_t aoff = (uint32_t)((mw * 64 + (q & 1) * 8 + lr) * SROW + (q >> 1) * 16);
    const uint32_t boff = (uint32_t)(TILEB + (nw * 32 + (q >> 1) * 8 + lr) * SROW + (q & 1) * 16);

    auto issue = [&](int c) {
        if (c < NCH) {
            uint32_t st = sb + (c % 3) * STAGEB;
            size_t gk = (size_t)c * (KC * 2);
            #pragma unroll
            for (int p = 0; p < 4; p++) {
                int idx = tid + p * 256;      // 0..1023
                int rr  = idx >> 3;           // 0..127
                int cc  = (idx & 7) * 16;     // 0..112
                cpasync16(st + rr * SROW + cc,
                          Ag + (size_t)rr * (KP * 2) + gk + cc);
                cpasync16(st + TILEB + rr * SROW + cc,
                          Bg + (size_t)rr * (KP * 2) + gk + cc);
            }
        }
        asm volatile("cp.async.commit_group;" ::: "memory");
    };

    uint32_t af[2][4][4], bf[2][4][2];

    auto ldA = [&](uint32_t st, int ks, uint32_t a_[4][4]) {
        #pragma unroll
        for (int i = 0; i < 4; i++)
            ldsm4(a_[i], st + aoff + i * 16 * SROW + ks * 32);
    };
    auto ldB = [&](uint32_t st, int ks, uint32_t b_[4][2]) {
        #pragma unroll
        for (int jj = 0; jj < 2; jj++) {
            uint32_t t4[4];
            ldsm4(t4, st + boff + jj * 16 * SROW + ks * 32);
            b_[jj * 2][0]     = t4[0]; b_[jj * 2][1]     = t4[1];
            b_[jj * 2 + 1][0] = t4[2]; b_[jj * 2 + 1][1] = t4[3];
        }
    };
    auto domma = [&](uint32_t a_[4][4], uint32_t b_[4][2]) {
        #pragma unroll
        for (int i = 0; i < 4; i++)
            #pragma unroll
            for (int j = 0; j < 4; j++)
                mma16816(acc[i][j], a_[i], b_[j]);
    };

    issue(0); issue(1);
    asm volatile("cp.async.wait_group 1;" ::: "memory");
    __syncthreads();
    ldA(sb, 0, af[0]); ldB(sb, 0, bf[0]);     // chunk 0, ks 0

    for (int c = 0; c < NCH; c++) {
        uint32_t stc = sb + (c % 3) * STAGEB;
        issue(c + 2);                          // into stage (c-1)%3 (free)
        #pragma unroll
        for (int ks = 0; ks < 4; ks++) {
            int cur = ks & 1, nxt = cur ^ 1;
            if (ks < 3) {
                ldA(stc, ks + 1, af[nxt]); ldB(stc, ks + 1, bf[nxt]);
            } else if (c + 1 < NCH) {
                asm volatile("cp.async.wait_group 1;" ::: "memory");
                __syncthreads();
                uint32_t stn = sb + ((c + 1) % 3) * STAGEB;
                ldA(stn, 0, af[nxt]); ldB(stn, 0, bf[nxt]);
            }
            domma(af[cur], bf[cur]);
        }
    }
}

// ---------------------------------------------------------------------------
// Kernel 1: proj via HMMA bf16x3; epilogue writes Apack = [hi|lo|hi] of proj.
// ---------------------------------------------------------------------------
__global__ __launch_bounds__(256, 2)
void proj_hmma(void)
{
    extern __shared__ __align__(128) char smem[];
    const int tid = threadIdx.x;
    const int rowBase = blockIdx.y * 128;
    const int colBase = blockIdx.x * 128;

    float acc[4][4][4];
    #pragma unroll
    for (int i = 0; i < 4; i++)
        #pragma unroll
        for (int j = 0; j < 4; j++)
            #pragma unroll
            for (int v = 0; v < 4; v++) acc[i][j][v] = 0.f;

    hmma_mainloop((const char*)(g_Bpack + (size_t)rowBase * KP),
                  (const char*)(g_Wpack + (size_t)colBase * KP),
                  smem, acc, tid);

    const int w = tid >> 5, l = tid & 31;
    const int mw = w >> 2, nw = w & 3;
    const int lq = l >> 2, lrm = l & 3;

    #pragma unroll
    for (int i = 0; i < 4; i++) {
        #pragma unroll
        for (int half = 0; half < 2; half++) {
            int row = rowBase + mw * 64 + i * 16 + lq + 8 * half;
            size_t base = (size_t)row * KP;
            #pragma unroll
            for (int j = 0; j < 4; j++) {
                int col = colBase + nw * 32 + j * 8 + lrm * 2;
                float x0 = acc[i][j][half * 2 + 0];
                float x1 = acc[i][j][half * 2 + 1];
                __nv_bfloat16 h0 = __float2bfloat16(x0);
                __nv_bfloat16 l0 = __float2bfloat16(x0 - __bfloat162float(h0));
                __nv_bfloat16 h1 = __float2bfloat16(x1);
                __nv_bfloat16 l1 = __float2bfloat16(x1 - __bfloat162float(h1));
                *(__nv_bfloat162*)(g_Apack + base + col)       = {h0, h1};
                *(__nv_bfloat162*)(g_Apack + base + 256 + col) = {l0, l1};
                *(__nv_bfloat162*)(g_Apack + base + 512 + col) = {h0, h1};
            }
        }
    }
}

// ---------------------------------------------------------------------------
// Kernel 2: att GEMM, sigmoid epilogue + att store + per-warp w reduction.
// ---------------------------------------------------------------------------
__global__ __launch_bounds__(256, 2)
void att_kernel(const float* __restrict__ mask, const float* __restrict__ aself,
                float* __restrict__ att_out)
{
    extern __shared__ __align__(128) char smem[];

    const int tid = threadIdx.x;
    const int w = tid >> 5, l = tid & 31;
    const int mw = w >> 2, nw = w & 3;
    const int b = blockIdx.z;
    const int rowBase = blockIdx.y * 128;
    const int colBase = blockIdx.x * 128;

    float acc[4][4][4];
    #pragma unroll
    for (int i = 0; i < 4; i++)
        #pragma unroll
        for (int j = 0; j < 4; j++)
            #pragma unroll
            for (int v = 0; v < 4; v++) acc[i][j][v] = 0.f;

    hmma_mainloop((const char*)(g_Apack + (size_t)(b * ROWS + rowBase) * KP),
                  (const char*)(g_Bpack + (size_t)(b * ROWS + colBase) * KP),
                  smem, acc, tid);

    // ---- epilogue ----
    const int lq = l >> 2, lrm = l & 3;
    const int ii  = blockIdx.y * 2 + mw;
    const int jjg = blockIdx.x * 2 + (nw >> 1);

    float asv[4][2];
    #pragma unroll
    for (int i = 0; i < 4; i++)
        #pragma unroll
        for (int h = 0; h < 2; h++)
            asv[i][h] = aself[b * ROWS + rowBase + mw * 64 + i * 16 + lq + 8 * h];

    float mc[4][2];
    #pragma unroll
    for (int j = 0; j < 4; j++) {
        int tc = nw * 32 + j * 8 + lrm * 2;
        mc[j][0] = (1.0f - mask[b * ROWS + colBase + tc])     * NEG_BIG;
        mc[j][1] = (1.0f - mask[b * ROWS + colBase + tc + 1]) * NEG_BIG;
    }

    float wpart[4][2];
    #pragma unroll
    for (int j = 0; j < 4; j++) { wpart[j][0] = 0.f; wpart[j][1] = 0.f; }

    float* attB = att_out + (((size_t)((b * Cv + ii) * Cv + jjg)) << 12);

    #pragma unroll
    for (int i = 0; i < 4; i++) {
        int s_lo = i * 16 + lq;
        #pragma unroll
        for (int j = 0; j < 4; j++) {
            int tcol = (nw & 1) * 32 + j * 8 + lrm * 2;
            float a0 = fast_sigmoid(acc[i][j][0] + mc[j][0]);
            float a1 = fast_sigmoid(acc[i][j][1] + mc[j][1]);
            float a2 = fast_sigmoid(acc[i][j][2] + mc[j][0]);
            float a3 = fast_sigmoid(acc[i][j][3] + mc[j][1]);
            *(float2*)(attB + (size_t)s_lo * 64 + tcol)       = make_float2(a0, a1);
            *(float2*)(attB + (size_t)(s_lo + 8) * 64 + tcol) = make_float2(a2, a3);
            wpart[j][0] += a0 * asv[i][0] + a2 * asv[i][1];
            wpart[j][1] += a1 * asv[i][0] + a3 * asv[i][1];
        }
    }

    #pragma unroll
    for (int d = 4; d <= 16; d <<= 1)
        #pragma unroll
        for (int j = 0; j < 4; j++) {
            wpart[j][0] += __shfl_xor_sync(0xffffffffu, wpart[j][0], d);
            wpart[j][1] += __shfl_xor_sync(0xffffffffu, wpart[j][1], d);
        }
    if (lq == 0) {
        #pragma unroll
        for (int j = 0; j < 4; j++) {
            int tcol = (nw & 1) * 32 + j * 8 + lrm * 2;
            *(float2*)(g_w + ((size_t)((b * Cv + ii) * Cv + jjg)) * 64 + tcol)
                = make_float2(wpart[j][0], wpart[j][1]);
        }
    }
}

// ---------------------------------------------------------------------------
// Kernel 3: fused[b,i,j,h] = sum_t w[b,i,j,t] * inputs[b,j,t,h]
// ---------------------------------------------------------------------------
__global__ __launch_bounds__(256)
void fused_kernel(const float* __restrict__ inp, float* __restrict__ fused)
{
    const int j  = blockIdx.x;
    const int b  = blockIdx.y;
    const int i0 = blockIdx.z * 8;
    const int h  = threadIdx.x;

    const float* X = inp + (size_t)((b * Cv + j) * Sv) * Hv;
    float xc[64];
    #pragma unroll
    for (int t = 0; t < 64; t++) xc[t] = X[(size_t)t * Hv + h];

    __shared__ float sw[8][64];
    #pragma unroll
    for (int p = 0; p < 2; p++) {
        int idx = h + p * 256;           // 0..511
        int qq = idx >> 6, t = idx & 63;
        sw[qq][t] = g_w[((b * Cv + (i0 + qq)) * Cv + j) * Sv + t];
    }
    __syncthreads();

    #pragma unroll
    for (int qq = 0; qq < 8; qq++) {
        float acc = 0.f;
        #pragma unroll
        for (int t = 0; t < 64; t++) acc = fmaf(sw[qq][t], xc[t], acc);
        fused[(size_t)((b * Cv + (i0 + qq)) * Cv + j) * Hv + h] = acc;
    }
}

// ---------------------------------------------------------------------------
extern "C" void kernel_launch(void* const* d_in, const int* in_sizes, int n_in,
                              void* d_out, int out_size)
{
    const float* inputs = (const float*)d_in[0];   // [B,C,S,H]
    const float* mask   = (const float*)d_in[1];   // [B,C,S]
    const float* aself  = (const float*)d_in[2];   // [B,C,S]
    const float* W      = (const float*)d_in[3];   // [H,H]

    float* fused = (float*)d_out;                                  // [B,C,C,H]
    float* att   = (float*)d_out + (size_t)Bv * Cv * Cv * Hv;      // [B,C,C,S,S]

    cudaFuncSetAttribute(proj_hmma, cudaFuncAttributeMaxDynamicSharedMemorySize,
                         SMEM_DYN);
    cudaFuncSetAttribute(att_kernel, cudaFuncAttributeMaxDynamicSharedMemorySize,
                         SMEM_DYN);

    pack_inputs<<<8192, 256>>>(inputs);
    pack_W<<<256, 256>>>(W);
    proj_hmma<<<dim3(2, 64, 1), 256, SMEM_DYN>>>();
    att_kernel<<<dim3(16, 16, Bv), 256, SMEM_DYN>>>(mask, aself, att);
    fused_kernel<<<dim3(Cv, Bv, 4), 256>>>(inputs, fused);
}

// round 12
// speedup vs baseline: 2.2447x; 1.0029x over previous
#include <cuda_runtime.h>
#include <cuda_bf16.h>
#include <math.h>
#include <stdint.h>

#define Bv 4
#define Cv 32
#define Sv 64
#define Hv 256
#define ROWS 2048
#define NEG_BIG (-1e10f)

#define KP 768            // packed K' = 3 * 256 bf16
#define KC 64             // bf16 per pipeline chunk (128B per row)
#define NCH 12            // KP / KC
#define SROW 144          // smem row stride in bytes (128B data + 16B pad)
#define TILEB (128 * SROW)        // 18432 B per operand tile
#define STAGEB (2 * TILEB)        // A + B per stage
#define NSTAGE 3
#define SMEM_DYN (NSTAGE * STAGEB)   // 110592 B

// ---- scratch (static device arrays) ----------------------------------------
__device__ __nv_bfloat16 g_Apack[(size_t)Bv * ROWS * KP];   // [hi | lo | hi] of proj
__device__ __nv_bfloat16 g_Bpack[(size_t)Bv * ROWS * KP];   // [hi | hi | lo] of inputs
__device__ __nv_bfloat16 g_Wpack[(size_t)Hv * KP];          // [hi | lo | hi] of W
__device__ float g_w[Bv * Cv * Cv * Sv];

// ---- helpers ---------------------------------------------------------------
__device__ __forceinline__ uint32_t s2u(const void* p) {
    uint32_t a;
    asm("{ .reg .u64 t; cvta.to.shared.u64 t, %1; cvt.u32.u64 %0, t; }"
        : "=r"(a) : "l"(p));
    return a;
}
__device__ __forceinline__ void cpasync16(uint32_t s, const void* g) {
    asm volatile("cp.async.cg.shared.global [%0], [%1], 16;" :: "r"(s), "l"(g));
}
__device__ __forceinline__ void ldsm4(uint32_t r[4], uint32_t addr) {
    asm volatile("ldmatrix.sync.aligned.m8n8.x4.shared.b16 {%0,%1,%2,%3}, [%4];"
        : "=r"(r[0]), "=r"(r[1]), "=r"(r[2]), "=r"(r[3]) : "r"(addr));
}
__device__ __forceinline__ void mma16816(float c[4], const uint32_t a[4],
                                         const uint32_t b[2]) {
    asm volatile(
        "mma.sync.aligned.m16n8k16.row.col.f32.bf16.bf16.f32 "
        "{%0,%1,%2,%3}, {%4,%5,%6,%7}, {%8,%9}, {%0,%1,%2,%3};"
        : "+f"(c[0]), "+f"(c[1]), "+f"(c[2]), "+f"(c[3])
        : "r"(a[0]), "r"(a[1]), "r"(a[2]), "r"(a[3]), "r"(b[0]), "r"(b[1]));
}

// ---- MUFU-free sigmoid (validated R4-R11) ----------------------------------
__device__ __forceinline__ float fast_sigmoid(float x) {
    x = fminf(30.0f, fmaxf(-30.0f, x));
    float t  = x * 1.4426950408889634f;
    float r  = t + 12582912.0f;
    float fi = r - 12582912.0f;
    float f  = t - fi;
    float p  = 1.3333558146428443e-3f;
    p = fmaf(p, f, 9.6181291076284772e-3f);
    p = fmaf(p, f, 5.5504108664821580e-2f);
    p = fmaf(p, f, 2.4022650695910072e-1f);
    p = fmaf(p, f, 6.9314718055994531e-1f);
    p = fmaf(p, f, 1.0f);
    int ei = __float_as_int(r) - 0x4B400000;
    float e = __int_as_float(__float_as_int(p) + (ei << 23));
    float d = 1.0f + e;
    float y = __int_as_float(0x7EF311C3 - __float_as_int(d));
    y = y * fmaf(-d, y, 2.0f);
    y = y * fmaf(-d, y, 2.0f);
    y = y * fmaf(-d, y, 2.0f);
    return e * y;
}

// ---------------------------------------------------------------------------
// Kernel 0a: pack inputs -> Bpack = [hi | hi | lo]
// ---------------------------------------------------------------------------
__global__ __launch_bounds__(256)
void pack_inputs(const float* __restrict__ inp)
{
    int idx = blockIdx.x * 256 + threadIdx.x;    // < Bv*ROWS*Hv = 2097152
    float x = inp[idx];
    __nv_bfloat16 hi = __float2bfloat16(x);
    __nv_bfloat16 lo = __float2bfloat16(x - __bfloat162float(hi));
    int row = idx >> 8, k = idx & 255;
    size_t base = (size_t)row * KP;
    g_Bpack[base + k]       = hi;
    g_Bpack[base + 256 + k] = hi;
    g_Bpack[base + 512 + k] = lo;
}

// ---------------------------------------------------------------------------
// Kernel 0b: pack W -> Wpack = [hi | lo | hi]
// ---------------------------------------------------------------------------
__global__ __launch_bounds__(256)
void pack_W(const float* __restrict__ W)
{
    int idx = blockIdx.x * 256 + threadIdx.x;    // < 65536
    float x = W[idx];
    __nv_bfloat16 hi = __float2bfloat16(x);
    __nv_bfloat16 lo = __float2bfloat16(x - __bfloat162float(hi));
    int row = idx >> 8, k = idx & 255;
    size_t base = (size_t)row * KP;
    g_Wpack[base + k]       = hi;
    g_Wpack[base + 256 + k] = lo;
    g_Wpack[base + 512 + k] = hi;
}

// ---------------------------------------------------------------------------
// Shared HMMA mainloop: 128x128 tile, K'=768, KC=64 chunks (4 ks-steps each),
// 3-stage cp.async ring, ONE barrier per chunk, register ping-pong fragments.
// 4 warps (128 threads), warp grid 2(M) x 2(N), warp tile 64x64.
// Per ks-step: 8 LDSM.x4 feed 32 HMMA (half the smem traffic of the 2x4 grid).
// ---------------------------------------------------------------------------
__device__ __forceinline__ void hmma_mainloop(
    const char* __restrict__ Ag, const char* __restrict__ Bg,
    char* smem, float acc[4][8][4], int tid)
{
    const int w = tid >> 5, l = tid & 31;
    const int mw = w >> 1, nw = w & 1;
    const uint32_t sb = s2u(smem);

    const int q = l >> 3, lr = l & 7;
    const uint32_t aoff = (uint32_t)((mw * 64 + (q & 1) * 8 + lr) * SROW + (q >> 1) * 16);
    const uint32_t boff = (uint32_t)(TILEB + (nw * 64 + (q >> 1) * 8 + lr) * SROW + (q & 1) * 16);

    auto issue = [&](int c) {
        if (c < NCH) {
            uint32_t st = sb + (c % 3) * STAGEB;
            size_t gk = (size_t)c * (KC * 2);
            #pragma unroll
            for (int p = 0; p < 8; p++) {
                int idx = tid + p * 128;      // 0..1023
                int rr  = idx >> 3;           // 0..127
                int cc  = (idx & 7) * 16;     // 0..112
                cpasync16(st + rr * SROW + cc,
                          Ag + (size_t)rr * (KP * 2) + gk + cc);
                cpasync16(st + TILEB + rr * SROW + cc,
                          Bg + (size_t)rr * (KP * 2) + gk + cc);
            }
        }
        asm volatile("cp.async.commit_group;" ::: "memory");
    };

    uint32_t af[2][4][4], bf[2][8][2];

    auto ldA = [&](uint32_t st, int ks, uint32_t a_[4][4]) {
        #pragma unroll
        for (int i = 0; i < 4; i++)
            ldsm4(a_[i], st + aoff + i * 16 * SROW + ks * 32);
    };
    auto ldB = [&](uint32_t st, int ks, uint32_t b_[8][2]) {
        #pragma unroll
        for (int jj = 0; jj < 4; jj++) {
            uint32_t t4[4];
            ldsm4(t4, st + boff + jj * 16 * SROW + ks * 32);
            b_[jj * 2][0]     = t4[0]; b_[jj * 2][1]     = t4[1];
            b_[jj * 2 + 1][0] = t4[2]; b_[jj * 2 + 1][1] = t4[3];
        }
    };
    auto domma = [&](uint32_t a_[4][4], uint32_t b_[8][2]) {
        #pragma unroll
        for (int i = 0; i < 4; i++)
            #pragma unroll
            for (int j = 0; j < 8; j++)
                mma16816(acc[i][j], a_[i], b_[j]);
    };

    issue(0); issue(1);
    asm volatile("cp.async.wait_group 1;" ::: "memory");
    __syncthreads();
    ldA(sb, 0, af[0]); ldB(sb, 0, bf[0]);     // chunk 0, ks 0

    for (int c = 0; c < NCH; c++) {
        uint32_t stc = sb + (c % 3) * STAGEB;
        issue(c + 2);                          // into stage (c-1)%3 (free)
        #pragma unroll
        for (int ks = 0; ks < 4; ks++) {
            int cur = ks & 1, nxt = cur ^ 1;
            if (ks < 3) {
                ldA(stc, ks + 1, af[nxt]); ldB(stc, ks + 1, bf[nxt]);
            } else if (c + 1 < NCH) {
                asm volatile("cp.async.wait_group 1;" ::: "memory");
                __syncthreads();
                uint32_t stn = sb + ((c + 1) % 3) * STAGEB;
                ldA(stn, 0, af[nxt]); ldB(stn, 0, bf[nxt]);
            }
            domma(af[cur], bf[cur]);
        }
    }
}

// ---------------------------------------------------------------------------
// Kernel 1: proj via HMMA bf16x3; epilogue writes Apack = [hi|lo|hi] of proj.
// ---------------------------------------------------------------------------
__global__ __launch_bounds__(128, 2)
void proj_hmma(void)
{
    extern __shared__ __align__(128) char smem[];
    const int tid = threadIdx.x;
    const int rowBase = blockIdx.y * 128;
    const int colBase = blockIdx.x * 128;

    float acc[4][8][4];
    #pragma unroll
    for (int i = 0; i < 4; i++)
        #pragma unroll
        for (int j = 0; j < 8; j++)
            #pragma unroll
            for (int v = 0; v < 4; v++) acc[i][j][v] = 0.f;

    hmma_mainloop((const char*)(g_Bpack + (size_t)rowBase * KP),
                  (const char*)(g_Wpack + (size_t)colBase * KP),
                  smem, acc, tid);

    const int w = tid >> 5, l = tid & 31;
    const int mw = w >> 1, nw = w & 1;
    const int lq = l >> 2, lrm = l & 3;

    #pragma unroll
    for (int i = 0; i < 4; i++) {
        #pragma unroll
        for (int half = 0; half < 2; half++) {
            int row = rowBase + mw * 64 + i * 16 + lq + 8 * half;
            size_t base = (size_t)row * KP;
            #pragma unroll
            for (int j = 0; j < 8; j++) {
                int col = colBase + nw * 64 + j * 8 + lrm * 2;
                float x0 = acc[i][j][half * 2 + 0];
                float x1 = acc[i][j][half * 2 + 1];
                __nv_bfloat16 h0 = __float2bfloat16(x0);
                __nv_bfloat16 l0 = __float2bfloat16(x0 - __bfloat162float(h0));
                __nv_bfloat16 h1 = __float2bfloat16(x1);
                __nv_bfloat16 l1 = __float2bfloat16(x1 - __bfloat162float(h1));
                *(__nv_bfloat162*)(g_Apack + base + col)       = {h0, h1};
                *(__nv_bfloat162*)(g_Apack + base + 256 + col) = {l0, l1};
                *(__nv_bfloat162*)(g_Apack + base + 512 + col) = {h0, h1};
            }
        }
    }
}

// ---------------------------------------------------------------------------
// Kernel 2: att GEMM, sigmoid epilogue + att store + per-warp w reduction.
// Each warp owns exactly one (i-sentence, j-sentence) pair of the tile.
// ---------------------------------------------------------------------------
__global__ __launch_bounds__(128, 2)
void att_kernel(const float* __restrict__ mask, const float* __restrict__ aself,
                float* __restrict__ att_out)
{
    extern __shared__ __align__(128) char smem[];

    const int tid = threadIdx.x;
    const int w = tid >> 5, l = tid & 31;
    const int mw = w >> 1, nw = w & 1;
    const int b = blockIdx.z;
    const int rowBase = blockIdx.y * 128;
    const int colBase = blockIdx.x * 128;

    float acc[4][8][4];
    #pragma unroll
    for (int i = 0; i < 4; i++)
        #pragma unroll
        for (int j = 0; j < 8; j++)
            #pragma unroll
            for (int v = 0; v < 4; v++) acc[i][j][v] = 0.f;

    hmma_mainloop((const char*)(g_Apack + (size_t)(b * ROWS + rowBase) * KP),
                  (const char*)(g_Bpack + (size_t)(b * ROWS + colBase) * KP),
                  smem, acc, tid);

    // ---- epilogue ----
    const int lq = l >> 2, lrm = l & 3;
    const int ii  = blockIdx.y * 2 + mw;
    const int jjg = blockIdx.x * 2 + nw;

    float asv[4][2];
    #pragma unroll
    for (int i = 0; i < 4; i++)
        #pragma unroll
        for (int h = 0; h < 2; h++)
            asv[i][h] = aself[b * ROWS + rowBase + mw * 64 + i * 16 + lq + 8 * h];

    float mc[8][2];
    #pragma unroll
    for (int j = 0; j < 8; j++) {
        int tc = nw * 64 + j * 8 + lrm * 2;
        mc[j][0] = (1.0f - mask[b * ROWS + colBase + tc])     * NEG_BIG;
        mc[j][1] = (1.0f - mask[b * ROWS + colBase + tc + 1]) * NEG_BIG;
    }

    float wpart[8][2];
    #pragma unroll
    for (int j = 0; j < 8; j++) { wpart[j][0] = 0.f; wpart[j][1] = 0.f; }

    float* attB = att_out + (((size_t)((b * Cv + ii) * Cv + jjg)) << 12);

    #pragma unroll
    for (int i = 0; i < 4; i++) {
        int s_lo = i * 16 + lq;
        #pragma unroll
        for (int j = 0; j < 8; j++) {
            int tcol = j * 8 + lrm * 2;
            float a0 = fast_sigmoid(acc[i][j][0] + mc[j][0]);
            float a1 = fast_sigmoid(acc[i][j][1] + mc[j][1]);
            float a2 = fast_sigmoid(acc[i][j][2] + mc[j][0]);
            float a3 = fast_sigmoid(acc[i][j][3] + mc[j][1]);
            *(float2*)(attB + (size_t)s_lo * 64 + tcol)       = make_float2(a0, a1);
            *(float2*)(attB + (size_t)(s_lo + 8) * 64 + tcol) = make_float2(a2, a3);
            wpart[j][0] += a0 * asv[i][0] + a2 * asv[i][1];
            wpart[j][1] += a1 * asv[i][0] + a3 * asv[i][1];
        }
    }

    #pragma unroll
    for (int d = 4; d <= 16; d <<= 1)
        #pragma unroll
        for (int j = 0; j < 8; j++) {
            wpart[j][0] += __shfl_xor_sync(0xffffffffu, wpart[j][0], d);
            wpart[j][1] += __shfl_xor_sync(0xffffffffu, wpart[j][1], d);
        }
    if (lq == 0) {
        #pragma unroll
        for (int j = 0; j < 8; j++) {
            int tcol = j * 8 + lrm * 2;
            *(float2*)(g_w + ((size_t)((b * Cv + ii) * Cv + jjg)) * 64 + tcol)
                = make_float2(wpart[j][0], wpart[j][1]);
        }
    }
}

// ---------------------------------------------------------------------------
// Kernel 3: fused[b,i,j,h] = sum_t w[b,i,j,t] * inputs[b,j,t,h]
// ---------------------------------------------------------------------------
__global__ __launch_bounds__(256)
void fused_kernel(const float* __restrict__ inp, float* __restrict__ fused)
{
    const int j  = blockIdx.x;
    const int b  = blockIdx.y;
    const int i0 = blockIdx.z * 8;
    const int h  = threadIdx.x;

    const float* X = inp + (size_t)((b * Cv + j) * Sv) * Hv;
    float xc[64];
    #pragma unroll
    for (int t = 0; t < 64; t++) xc[t] = X[(size_t)t * Hv + h];

    __shared__ float sw[8][64];
    #pragma unroll
    for (int p = 0; p < 2; p++) {
        int idx = h + p * 256;           // 0..511
        int qq = idx >> 6, t = idx & 63;
        sw[qq][t] = g_w[((b * Cv + (i0 + qq)) * Cv + j) * Sv + t];
    }
    __syncthreads();

    #pragma unroll
    for (int qq = 0; qq < 8; qq++) {
        float acc = 0.f;
        #pragma unroll
        for (int t = 0; t < 64; t++) acc = fmaf(sw[qq][t], xc[t], acc);
        fused[(size_t)((b * Cv + (i0 + qq)) * Cv + j) * Hv + h] = acc;
    }
}

// ---------------------------------------------------------------------------
extern "C" void kernel_launch(void* const* d_in, const int* in_sizes, int n_in,
                              void* d_out, int out_size)
{
    const float* inputs = (const float*)d_in[0];   // [B,C,S,H]
    const float* mask   = (const float*)d_in[1];   // [B,C,S]
    const float* aself  = (const float*)d_in[2];   // [B,C,S]
    const float* W      = (const float*)d_in[3];   // [H,H]

    float* fused = (float*)d_out;                                  // [B,C,C,H]
    float* att   = (float*)d_out + (size_t)Bv * Cv * Cv * Hv;      // [B,C,C,S,S]

    cudaFuncSetAttribute(proj_hmma, cudaFuncAttributeMaxDynamicSharedMemorySize,
                         SMEM_DYN);
    cudaFuncSetAttribute(att_kernel, cudaFuncAttributeMaxDynamicSharedMemorySize,
                         SMEM_DYN);

    pack_inputs<<<8192, 256>>>(inputs);
    pack_W<<<256, 256>>>(W);
    proj_hmma<<<dim3(2, 64, 1), 128, SMEM_DYN>>>();
    att_kernel<<<dim3(16, 16, Bv), 128, SMEM_DYN>>>(mask, aself, att);
    fused_kernel<<<dim3(Cv, Bv, 4), 256>>>(inputs, fused);
}